// round 11
// baseline (speedup 1.0000x reference)
#include <cuda_runtime.h>
#include <cuda_fp16.h>
#include <math.h>
#include <stdint.h>

#define T_STEPS 8
#define NN      20000
#define FIN_DIM 32
#define EE      160000
#define HID     128
#define G3      384
#define TN      (T_STEPS * NN)
#define TE      (T_STEPS * EE)
#define SCALE   0.08838834764831845f
#define LVL_SC  2048.0f
#define LVL_INV (1.0f / 2048.0f)
#define SCAN_B  1024
#define NBLK_SCAN ((TN + SCAN_B - 1) / SCAN_B)

typedef unsigned long long u64;

// ------------------------- scratch (device globals) -------------------------
__device__ float g_h[(size_t)TN * HID];
__device__ float g_tmp[(size_t)TN * HID];
__device__ float g_q[(size_t)TN * HID];
__device__ float g_k[(size_t)TN * HID];
__device__ float g_v[(size_t)TN * HID];
__device__ float g_gi[(size_t)TN * G3];
__device__ float g_gh[(size_t)NN * G3];
__device__ float g_hprev[(size_t)NN * HID];
__device__ float g_qs[NN], g_ks[NN], g_vs[NN];
__device__ __align__(16) __half g_wprep[385024];   // 2-level fp16 split weights
// CSR
__device__ int   g_cnt[TN];
__device__ int   g_start[TN];
__device__ int   g_cur[TN];
__device__ int   g_bsum[NBLK_SCAN + 8];
__device__ int   g_csrc[TE];
__device__ float g_cea[TE];

#define WIH 0        // level stride 12288
#define WHH 24576    // level stride 49152
#define WQ  122880   // level stride 32768
#define WK  188416
#define WV  253952
#define WS  319488

// ------------------------------- helpers ------------------------------------
__device__ __forceinline__ float warp_sum(float v) {
#pragma unroll
    for (int o = 16; o; o >>= 1) v += __shfl_xor_sync(0xffffffffu, v, o);
    return v;
}
__device__ __forceinline__ float warp_max(float v) {
#pragma unroll
    for (int o = 16; o; o >>= 1) v = fmaxf(v, __shfl_xor_sync(0xffffffffu, v, o));
    return v;
}
__device__ __forceinline__ float dot4(float4 a, float4 b) {
    return a.x * b.x + a.y * b.y + a.z * b.z + a.w * b.w;
}
__device__ __forceinline__ float sigf(float x) { return 1.0f / (1.0f + expf(-x)); }

// ---------------- mma.sync GEMM (fp16 2-level, 3-pass; 64-row tile) ----------
#define ROWB 272
#define ALVL (64 * ROWB)          // 17408 B per A level
#define BLVL (128 * ROWB)         // 34816 B per B level
#define SB_OFF (2 * ALVL)         // B starts after 2 A levels
#define SM_BYTES (2 * ALVL + 2 * BLVL)   // 104448 -> 2 CTAs/SM

struct PArgs {
    const __half* w[4];
    int lvl[4];
    const float* bias[4];
    float* out[4];
    int col[4];
    int ldc[4];
};

__device__ __forceinline__ void mma16816(float* c, const uint32_t* a, const uint32_t* b) {
    asm volatile(
        "mma.sync.aligned.m16n8k16.row.col.f32.f16.f16.f32 "
        "{%0,%1,%2,%3},{%4,%5,%6,%7},{%8,%9},{%0,%1,%2,%3};"
        : "+f"(c[0]), "+f"(c[1]), "+f"(c[2]), "+f"(c[3])
        : "r"(a[0]), "r"(a[1]), "r"(a[2]), "r"(a[3]), "r"(b[0]), "r"(b[1]));
}
__device__ __forceinline__ void ldsm_x4(uint32_t& r0, uint32_t& r1, uint32_t& r2, uint32_t& r3,
                                        uint32_t addr) {
    asm volatile("ldmatrix.sync.aligned.m8n8.x4.shared.b16 {%0,%1,%2,%3},[%4];"
                 : "=r"(r0), "=r"(r1), "=r"(r2), "=r"(r3) : "r"(addr));
}
__device__ __forceinline__ void ldsm_x2(uint32_t& r0, uint32_t& r1, uint32_t addr) {
    asm volatile("ldmatrix.sync.aligned.m8n8.x2.shared.b16 {%0,%1},[%2];"
                 : "=r"(r0), "=r"(r1) : "r"(addr));
}
__device__ __forceinline__ uint32_t smem_addr32(const void* p) {
    return (uint32_t)__cvta_generic_to_shared(p);
}

// gi/hprev/hout non-null => GRU mode: after GEMM, fuse gate computation.
__global__ void __launch_bounds__(256, 2) mma_gemm(
    PArgs pa, const float* __restrict__ A, int nrows, int K, int np,
    const float* __restrict__ gi, float* __restrict__ hprev, float* __restrict__ hout)
{
    extern __shared__ char sm[];
    const uint32_t smu = smem_addr32(sm);
    const int tid = threadIdx.x, wid = tid >> 5, lane = tid & 31;
    const int brow = blockIdx.x << 6;
    const int kshift = (K == 32) ? 5 : 7;

    const int wm = (wid & 1) * 32;
    const int wn = (wid >> 1) * 32;
    const uint32_t aoff = (uint32_t)((lane & 15) * ROWB + ((lane >> 4) & 1) * 16);
    const uint32_t boff = (uint32_t)((lane & 7) * ROWB + ((lane >> 3) & 1) * 16);

    // ---- stage A once: fp32 -> 2 fp16 levels (level 1 scaled x2048) ----
    for (int base = tid * 8; base < (64 << kshift); base += 2048) {
        const int row = base >> kshift;
        const int col = base & (K - 1);
        const int gr = brow + row;
        float4 x0 = make_float4(0.f, 0.f, 0.f, 0.f), x1 = x0;
        if (gr < nrows) {
            const float* src = A + (size_t)gr * K + col;
            x0 = *(const float4*)src;
            x1 = *(const float4*)(src + 4);
        }
        const float av[8] = {x0.x, x0.y, x0.z, x0.w, x1.x, x1.y, x1.z, x1.w};
        uint32_t p0[4], p1[4];
#pragma unroll
        for (int j = 0; j < 4; j++) {
            float a0 = av[2 * j], a1 = av[2 * j + 1];
            __half h0 = __float2half_rn(a0), h1 = __float2half_rn(a1);
            float r0 = (a0 - __half2float(h0)) * LVL_SC;
            float r1 = (a1 - __half2float(h1)) * LVL_SC;
            union { __half2 h; uint32_t u; } uh, ul;
            uh.h = __halves2half2(h0, h1);
            ul.h = __halves2half2(__float2half_rn(r0), __float2half_rn(r1));
            p0[j] = uh.u; p1[j] = ul.u;
        }
        char* dst = sm + row * ROWB + col * 2;
        *(uint4*)(dst) = make_uint4(p0[0], p0[1], p0[2], p0[3]);
        *(uint4*)(dst + ALVL) = make_uint4(p1[0], p1[1], p1[2], p1[3]);
    }

    const int nb = (128 << kshift) >> 3;   // uint4 per B level

    for (int p = 0; p < np; p++) {
        __syncthreads();
        const __half* W0 = pa.w[p];
        const int lvl = pa.lvl[p];
#pragma unroll
        for (int lv = 0; lv < 2; lv++) {
            const __half* Wl = W0 + (size_t)lv * lvl;
            char* dstb = sm + SB_OFF + lv * BLVL;
            for (int i = tid; i < nb; i += 256) {
                const int e = i * 8;
                const int row = e >> kshift;
                const int col = e & (K - 1);
                *(uint4*)(dstb + row * ROWB + col * 2) =
                    *(const uint4*)(Wl + (size_t)row * K + col);
            }
        }
        __syncthreads();

        float acc0[2][4][4], acc1[2][4][4];
#pragma unroll
        for (int i = 0; i < 2; i++)
#pragma unroll
            for (int j = 0; j < 4; j++)
#pragma unroll
                for (int r = 0; r < 4; r++) { acc0[i][j][r] = 0.0f; acc1[i][j][r] = 0.0f; }

        const int nk = K >> 4;
        for (int ks = 0; ks < nk; ks++) {
            const uint32_t k2 = (uint32_t)(ks << 5);
            uint32_t bf0[4][2], bf1[4][2];
            {
                const uint32_t bb0 = smu + SB_OFF + k2 + boff;
                const uint32_t bb1 = bb0 + BLVL;
#pragma unroll
                for (int nt = 0; nt < 4; nt++) {
                    ldsm_x2(bf0[nt][0], bf0[nt][1], bb0 + (uint32_t)((wn + nt * 8) * ROWB));
                    ldsm_x2(bf1[nt][0], bf1[nt][1], bb1 + (uint32_t)((wn + nt * 8) * ROWB));
                }
            }
            uint32_t af[2][4];
            {   // A level 0: acc0 += A0*B0 ; acc1 += A0*B1'
                const uint32_t ab = smu + k2 + aoff;
#pragma unroll
                for (int mt = 0; mt < 2; mt++)
                    ldsm_x4(af[mt][0], af[mt][1], af[mt][2], af[mt][3],
                            ab + (uint32_t)((wm + mt * 16) * ROWB));
#pragma unroll
                for (int mt = 0; mt < 2; mt++)
#pragma unroll
                    for (int nt = 0; nt < 4; nt++) {
                        mma16816(acc0[mt][nt], af[mt], bf0[nt]);
                        mma16816(acc1[mt][nt], af[mt], bf1[nt]);
                    }
            }
            {   // A level 1': acc1 += A1'*B0
                const uint32_t ab = smu + ALVL + k2 + aoff;
#pragma unroll
                for (int mt = 0; mt < 2; mt++)
                    ldsm_x4(af[mt][0], af[mt][1], af[mt][2], af[mt][3],
                            ab + (uint32_t)((wm + mt * 16) * ROWB));
#pragma unroll
                for (int mt = 0; mt < 2; mt++)
#pragma unroll
                    for (int nt = 0; nt < 4; nt++)
                        mma16816(acc1[mt][nt], af[mt], bf0[nt]);
            }
        }

        float* Co = pa.out[p];
        const float* bs = pa.bias[p];
        const int ld = pa.ldc[p], cb = pa.col[p];
#pragma unroll
        for (int nt = 0; nt < 4; nt++) {
            const int cloc = wn + nt * 8 + (lane & 3) * 2;
            const float b0 = bs[cloc], b1 = bs[cloc + 1];
#pragma unroll
            for (int mt = 0; mt < 2; mt++) {
                const int r0 = brow + wm + mt * 16 + (lane >> 2);
                if (r0 < nrows) {
                    float2 o = make_float2(acc0[mt][nt][0] + acc1[mt][nt][0] * LVL_INV + b0,
                                           acc0[mt][nt][1] + acc1[mt][nt][1] * LVL_INV + b1);
                    *(float2*)(Co + (size_t)r0 * ld + cb + cloc) = o;
                }
                const int r1 = r0 + 8;
                if (r1 < nrows) {
                    float2 o = make_float2(acc0[mt][nt][2] + acc1[mt][nt][2] * LVL_INV + b0,
                                           acc0[mt][nt][3] + acc1[mt][nt][3] * LVL_INV + b1);
                    *(float2*)(Co + (size_t)r1 * ld + cb + cloc) = o;
                }
            }
        }
    }

    // ---- fused GRU gate (CTA-local rows; gh just written is block-visible) ----
    if (gi != nullptr) {
        __syncthreads();
        const float* gh = pa.out[0];
        for (int i = tid; i < 64 * 32; i += 256) {
            const int row = i >> 5;
            const int n = brow + row;
            if (n >= nrows) break;
            const int c4 = (i & 31) << 2;
            const float* gin = gi + (size_t)n * G3;
            const float* ghn = gh + (size_t)n * G3;
            float4 ir = *(const float4*)(gin + c4);
            float4 iz = *(const float4*)(gin + 128 + c4);
            float4 in_ = *(const float4*)(gin + 256 + c4);
            float4 hr = *(const float4*)(ghn + c4);
            float4 hz = *(const float4*)(ghn + 128 + c4);
            float4 hn_ = *(const float4*)(ghn + 256 + c4);
            float4 hp = *(const float4*)(hprev + (size_t)n * HID + c4);
            float4 o;
            {
                float r = sigf(ir.x + hr.x), z = sigf(iz.x + hz.x);
                float nn = tanhf(in_.x + r * hn_.x);
                o.x = (1.0f - z) * nn + z * hp.x;
            }
            {
                float r = sigf(ir.y + hr.y), z = sigf(iz.y + hz.y);
                float nn = tanhf(in_.y + r * hn_.y);
                o.y = (1.0f - z) * nn + z * hp.y;
            }
            {
                float r = sigf(ir.z + hr.z), z = sigf(iz.z + hz.z);
                float nn = tanhf(in_.z + r * hn_.z);
                o.z = (1.0f - z) * nn + z * hp.z;
            }
            {
                float r = sigf(ir.w + hr.w), z = sigf(iz.w + hz.w);
                float nn = tanhf(in_.w + r * hn_.w);
                o.w = (1.0f - z) * nn + z * hp.w;
            }
            *(float4*)(hprev + (size_t)n * HID + c4) = o;
            *(float4*)(hout + (size_t)n * HID + c4) = o;
        }
    }
}

// -------------------- merged weight prep (fp32 -> 2x fp16) -------------------
struct WPArgs { const float* src[6]; int n[6]; int base[6]; };

__global__ void wprep_all(WPArgs wa, __half* __restrict__ wp)
{
    int seg = blockIdx.y;
    int i = blockIdx.x * blockDim.x + threadIdx.x;
    if (i >= wa.n[seg]) return;
    float x = wa.src[seg][i];
    __half h = __float2half_rn(x);
    float r = (x - __half2float(h)) * LVL_SC;
    __half* w = wp + wa.base[seg];
    int n = wa.n[seg];
    w[i] = h;
    w[n + i] = __float2half_rn(r);
}

// ------------------------------- CSR build -----------------------------------
__global__ void csr_count(const int* __restrict__ ei, int* __restrict__ cnt)
{
    int w = blockIdx.x * blockDim.x + threadIdx.x;
    if (w >= TE) return;
    int t = w / EE, e = w - t * EE;
    int d = ei[(size_t)t * 2 * EE + EE + e] + t * NN;
    atomicAdd(&cnt[d], 1);
}

__global__ void __launch_bounds__(SCAN_B) scan1(
    const int* __restrict__ cnt, int* __restrict__ incl, int* __restrict__ bsum)
{
    __shared__ int sh[SCAN_B];
    int g = blockIdx.x * SCAN_B + threadIdx.x;
    int v = (g < TN) ? cnt[g] : 0;
    sh[threadIdx.x] = v;
    __syncthreads();
#pragma unroll
    for (int off = 1; off < SCAN_B; off <<= 1) {
        int add = (threadIdx.x >= off) ? sh[threadIdx.x - off] : 0;
        __syncthreads();
        sh[threadIdx.x] += add;
        __syncthreads();
    }
    if (g < TN) incl[g] = sh[threadIdx.x];
    if (threadIdx.x == SCAN_B - 1) bsum[blockIdx.x] = sh[SCAN_B - 1];
}

__global__ void __launch_bounds__(256) scan2(int* __restrict__ bsum)
{
    __shared__ int sh[256];
    int v = (threadIdx.x < NBLK_SCAN) ? bsum[threadIdx.x] : 0;
    sh[threadIdx.x] = v;
    __syncthreads();
#pragma unroll
    for (int off = 1; off < 256; off <<= 1) {
        int add = (threadIdx.x >= off) ? sh[threadIdx.x - off] : 0;
        __syncthreads();
        sh[threadIdx.x] += add;
        __syncthreads();
    }
    if (threadIdx.x < NBLK_SCAN) bsum[threadIdx.x] = sh[threadIdx.x] - v;
}

__global__ void scan3(const int* __restrict__ cnt, const int* __restrict__ incl,
                      const int* __restrict__ bsum, int* __restrict__ start,
                      int* __restrict__ cur)
{
    int g = blockIdx.x * blockDim.x + threadIdx.x;
    if (g >= TN) return;
    int s = incl[g] - cnt[g] + bsum[g / SCAN_B];
    start[g] = s;
    cur[g] = s;
}

__global__ void csr_scatter(const int* __restrict__ ei, const float* __restrict__ ea,
                            int* __restrict__ cur, int* __restrict__ csrc,
                            float* __restrict__ cea)
{
    int w = blockIdx.x * blockDim.x + threadIdx.x;
    if (w >= TE) return;
    int t = w / EE, e = w - t * EE;
    const int* eib = ei + (size_t)t * 2 * EE;
    int s = eib[e] + t * NN;
    int d = eib[EE + e] + t * NN;
    int pos = atomicAdd(&cur[d], 1);
    csrc[pos] = s;
    cea[pos] = ea[w];
}

// -------------- fused conv edge phase: warp/dst, streaming softmax -----------
__global__ void __launch_bounds__(256) conv_edge(
    const float* __restrict__ q, const float* __restrict__ k,
    const float* __restrict__ v, const float* __restrict__ We,
    const int* __restrict__ start, const int* __restrict__ cnt,
    const int* __restrict__ csrc, const float* __restrict__ cea,
    float* __restrict__ out)
{
    int n = (blockIdx.x * blockDim.x + threadIdx.x) >> 5;
    int lane = threadIdx.x & 31;
    if (n >= TN) return;
    const int i4 = lane << 2;
    float4 qv = *(const float4*)(q + (size_t)n * HID + i4);
    float4 wev = *(const float4*)(We + i4);
    float qwe = warp_sum(dot4(qv, wev)) * SCALE;

    const int s0 = start[n], c = cnt[n];
    float mx = -INFINITY, denom = 0.0f, coef = 0.0f;
    float4 macc = make_float4(0.f, 0.f, 0.f, 0.f);

    for (int j = s0; j < s0 + c; j++) {
        int s = csrc[j];
        float eav = cea[j];
        float4 kv = *(const float4*)(k + (size_t)s * HID + i4);
        float p = warp_sum(dot4(qv, kv));
        float al = p * SCALE + eav * qwe;
        float4 vv = *(const float4*)(v + (size_t)s * HID + i4);
        if (al > mx) {
            float sc = expf(mx - al);
            denom *= sc; coef *= sc;
            macc.x *= sc; macc.y *= sc; macc.z *= sc; macc.w *= sc;
            mx = al;
        }
        float a = expf(al - mx);
        denom += a;
        coef += a * eav;
        macc.x += a * vv.x; macc.y += a * vv.y; macc.z += a * vv.z; macc.w += a * vv.w;
    }

    float inv = 1.0f / (denom + 1e-16f);
    float4 sk = *(const float4*)(out + (size_t)n * HID + i4);
    float4 o;
    o.x = sk.x + (macc.x + coef * wev.x) * inv;
    o.y = sk.y + (macc.y + coef * wev.y) * inv;
    o.z = sk.z + (macc.z + coef * wev.z) * inv;
    o.w = sk.w + (macc.w + coef * wev.w) * inv;
    o.x = o.x > 0.f ? o.x : 0.01f * o.x;
    o.y = o.y > 0.f ? o.y : 0.01f * o.y;
    o.z = o.z > 0.f ? o.z : 0.01f * o.z;
    o.w = o.w > 0.f ? o.w : 0.01f * o.w;
    *(float4*)(out + (size_t)n * HID + i4) = o;
}

// ------- fused temporal attention + top-3 + output-conv projections ----------
__global__ void __launch_bounds__(256) attn_outproj(
    const float* __restrict__ h, const float* __restrict__ W,
    const float* __restrict__ b,
    const float* __restrict__ Wq, const float* __restrict__ bq,
    const float* __restrict__ Wk, const float* __restrict__ bk,
    const float* __restrict__ Wv, const float* __restrict__ bv,
    const float* __restrict__ Ws, const float* __restrict__ bs,
    float* __restrict__ qs, float* __restrict__ ks,
    float* __restrict__ vs, float* __restrict__ outp)
{
    int n = (blockIdx.x * blockDim.x + threadIdx.x) >> 5;
    int lane = threadIdx.x & 31;
    if (n >= NN) return;
    const int i4 = lane << 2;
    float4 wv = *(const float4*)(W + i4);
    float4 hv[T_STEPS];
    float s[T_STEPS];
#pragma unroll
    for (int t = 0; t < T_STEPS; t++) {
        hv[t] = *(const float4*)(h + ((size_t)t * NN + n) * HID + i4);
        s[t] = warp_sum(dot4(hv[t], wv)) + b[0];
    }
    float mx = s[0];
#pragma unroll
    for (int t = 1; t < T_STEPS; t++) mx = fmaxf(mx, s[t]);
    float aw[T_STEPS]; float tot = 0.0f;
#pragma unroll
    for (int t = 0; t < T_STEPS; t++) { aw[t] = expf(s[t] - mx); tot += aw[t]; }
    float inv = 1.0f / tot;
#pragma unroll
    for (int t = 0; t < T_STEPS; t++) aw[t] *= inv;
    bool sel[T_STEPS];
#pragma unroll
    for (int t = 0; t < T_STEPS; t++) sel[t] = false;
    float sum3 = 0.0f;
#pragma unroll
    for (int r = 0; r < 3; r++) {
        float best = -1.0f; int bi = 0;
#pragma unroll
        for (int t = 0; t < T_STEPS; t++)
            if (!sel[t] && aw[t] > best) { best = aw[t]; bi = t; }
        sel[bi] = true; sum3 += best;
    }
    float winv = 1.0f / (sum3 + 1e-8f);
    float4 acc = make_float4(0.f, 0.f, 0.f, 0.f);
#pragma unroll
    for (int t = 0; t < T_STEPS; t++) {
        float w = sel[t] ? aw[t] * winv : 0.0f;
        acc.x += w * hv[t].x; acc.y += w * hv[t].y;
        acc.z += w * hv[t].z; acc.w += w * hv[t].w;
    }
    float4 wq = *(const float4*)(Wq + i4);
    float4 wk = *(const float4*)(Wk + i4);
    float4 wvv = *(const float4*)(Wv + i4);
    float4 ws = *(const float4*)(Ws + i4);
    float pq = warp_sum(dot4(acc, wq));
    float pk = warp_sum(dot4(acc, wk));
    float pv = warp_sum(dot4(acc, wvv));
    float ps = warp_sum(dot4(acc, ws));
    if (lane == 0) {
        qs[n] = pq + bq[0];
        ks[n] = pk + bk[0];
        vs[n] = pv + bv[0];
        outp[n] = ps + bs[0];
    }
}

// fused output-conv edge phase (warp/dst, lanes over edges, reuses t=7 CSR)
__global__ void __launch_bounds__(256) oc_edge(
    const float* __restrict__ qs, const float* __restrict__ ks,
    const float* __restrict__ vs, const float* __restrict__ We,
    const int* __restrict__ start, const int* __restrict__ cnt,
    const int* __restrict__ csrc, const float* __restrict__ cea,
    float* __restrict__ outp)
{
    int n = (blockIdx.x * blockDim.x + threadIdx.x) >> 5;
    int lane = threadIdx.x & 31;
    if (n >= NN) return;
    const int g = (T_STEPS - 1) * NN + n;
    const int s0 = start[g], c = cnt[g];
    if (c == 0) return;
    const float qsn = qs[n];
    const float we0 = We[0];

    float mx = -INFINITY;
    for (int j = s0 + lane; j < s0 + c; j += 32) {
        int sl = csrc[j] - (T_STEPS - 1) * NN;
        float al = qsn * (ks[sl] + cea[j] * we0);
        mx = fmaxf(mx, al);
    }
    mx = warp_max(mx);

    float dsum = 0.f, msum = 0.f;
    for (int j = s0 + lane; j < s0 + c; j += 32) {
        int sl = csrc[j] - (T_STEPS - 1) * NN;
        float eav = cea[j];
        float al = qsn * (ks[sl] + eav * we0);
        float a = expf(al - mx);
        dsum += a;
        msum += a * (vs[sl] + eav * we0);
    }
    dsum = warp_sum(dsum);
    msum = warp_sum(msum);
    if (lane == 0) outp[n] += msum / (dsum + 1e-16f);
}

// --------------------------------- host --------------------------------------
static float* symf(const void* sym) { void* p = nullptr; cudaGetSymbolAddress(&p, sym); return (float*)p; }

extern "C" void kernel_launch(void* const* d_in, const int* in_sizes, int n_in,
                              void* d_out, int out_size)
{
    const float* x_seq = (const float*)d_in[0];
    const int*   ei    = (const int*)d_in[1];
    const float* ea    = (const float*)d_in[2];
    const float* W_ih  = (const float*)d_in[3];
    const float* W_hh  = (const float*)d_in[4];
    const float* b_ih  = (const float*)d_in[5];
    const float* b_hh  = (const float*)d_in[6];
    const float* cWq = (const float*)d_in[7];  const float* cbq = (const float*)d_in[8];
    const float* cWk = (const float*)d_in[9];  const float* cbk = (const float*)d_in[10];
    const float* cWv = (const float*)d_in[11]; const float* cbv = (const float*)d_in[12];
    const float* cWe = (const float*)d_in[13];
    const float* cWs = (const float*)d_in[14]; const float* cbs = (const float*)d_in[15];
    const float* oWq = (const float*)d_in[16]; const float* obq = (const float*)d_in[17];
    const float* oWk = (const float*)d_in[18]; const float* obk = (const float*)d_in[19];
    const float* oWv = (const float*)d_in[20]; const float* obv = (const float*)d_in[21];
    const float* oWe = (const float*)d_in[22];
    const float* oWs = (const float*)d_in[23]; const float* obs = (const float*)d_in[24];
    const float* aW  = (const float*)d_in[25]; const float* ab  = (const float*)d_in[26];
    float* outp = (float*)d_out;

    float* ph     = symf(g_h);
    float* ptmp   = symf(g_tmp);
    float* pq     = symf(g_q);
    float* pk     = symf(g_k);
    float* pv     = symf(g_v);
    float* pgi    = symf(g_gi);
    float* pgh    = symf(g_gh);
    float* phprev = symf(g_hprev);
    float* pqs    = symf(g_qs);
    float* pks    = symf(g_ks);
    float* pvs    = symf(g_vs);
    int*   pcnt   = (int*)symf(g_cnt);
    int*   pstart = (int*)symf(g_start);
    int*   pcur   = (int*)symf(g_cur);
    int*   pbsum  = (int*)symf(g_bsum);
    int*   pcsrc  = (int*)symf(g_csrc);
    float* pcea   = symf(g_cea);
    __half* wp    = (__half*)symf(g_wprep);

    cudaFuncSetAttribute(mma_gemm, cudaFuncAttributeMaxDynamicSharedMemorySize, SM_BYTES);

    const int nwblk  = (NN + 7) / 8;
    const int tnwblk = (TN + 7) / 8;
    const int teblk  = (TE + 255) / 256;
    const int tnblk  = (TN + 255) / 256;

    // ---------------- weight prep ----------------
    {
        WPArgs wa;
        wa.src[0] = W_ih; wa.n[0] = 12288; wa.base[0] = WIH;
        wa.src[1] = W_hh; wa.n[1] = 49152; wa.base[1] = WHH;
        wa.src[2] = cWq;  wa.n[2] = 32768; wa.base[2] = WQ;
        wa.src[3] = cWk;  wa.n[3] = 32768; wa.base[3] = WK;
        wa.src[4] = cWv;  wa.n[4] = 32768; wa.base[4] = WV;
        wa.src[5] = cWs;  wa.n[5] = 32768; wa.base[5] = WS;
        wprep_all<<<dim3((49152 + 255) / 256, 6), 256>>>(wa, wp);
    }

    // ---------------- GRU ----------------
    cudaMemsetAsync(phprev, 0, (size_t)NN * HID * sizeof(float));
    {
        PArgs pa;
        for (int p = 0; p < 3; p++) {
            pa.w[p] = wp + WIH + (size_t)p * 128 * 32;
            pa.lvl[p] = 12288;
            pa.bias[p] = b_ih + p * 128;
            pa.out[p] = pgi; pa.col[p] = p * 128; pa.ldc[p] = G3;
        }
        pa.w[3] = pa.w[2]; pa.lvl[3] = 12288; pa.bias[3] = pa.bias[2];
        pa.out[3] = pgi; pa.col[3] = 256; pa.ldc[3] = G3;
        mma_gemm<<<(TN + 63) / 64, 256, SM_BYTES>>>(pa, x_seq, TN, 32, 3,
                                                    nullptr, nullptr, nullptr);
    }
    {
        PArgs pa;
        for (int p = 0; p < 3; p++) {
            pa.w[p] = wp + WHH + (size_t)p * 128 * 128;
            pa.lvl[p] = 49152;
            pa.bias[p] = b_hh + p * 128;
            pa.out[p] = pgh; pa.col[p] = p * 128; pa.ldc[p] = G3;
        }
        pa.w[3] = pa.w[2]; pa.lvl[3] = 49152; pa.bias[3] = pa.bias[2];
        pa.out[3] = pgh; pa.col[3] = 256; pa.ldc[3] = G3;
        for (int t = 0; t < T_STEPS; t++) {
            mma_gemm<<<(NN + 63) / 64, 256, SM_BYTES>>>(
                pa, phprev, NN, 128, 3,
                pgi + (size_t)t * NN * G3, phprev, ph + (size_t)t * NN * HID);
        }
    }

    // ---------------- CSR build ----------------
    cudaMemsetAsync(pcnt, 0, TN * sizeof(int));
    csr_count<<<teblk, 256>>>(ei, pcnt);
    scan1<<<NBLK_SCAN, SCAN_B>>>(pcnt, pcur, pbsum);
    scan2<<<1, 256>>>(pbsum);
    scan3<<<tnblk, 256>>>(pcnt, pcur, pbsum, pstart, pcur);
    csr_scatter<<<teblk, 256>>>(ei, ea, pcur, pcsrc, pcea);

    // ---------------- GNN: 2 layers, batched over all T ----------------
    for (int l = 0; l < 2; l++) {
        const float* in  = (l == 0) ? ph : ptmp;
        float*       out = (l == 0) ? ptmp : ph;
        const float* We = cWe + (size_t)l * HID;
        size_t lo = (size_t)l * 16384;

        PArgs pa;
        pa.w[0] = wp + WQ + lo; pa.lvl[0] = 32768; pa.bias[0] = cbq + l * 128;
        pa.out[0] = pq;  pa.col[0] = 0; pa.ldc[0] = 128;
        pa.w[1] = wp + WK + lo; pa.lvl[1] = 32768; pa.bias[1] = cbk + l * 128;
        pa.out[1] = pk;  pa.col[1] = 0; pa.ldc[1] = 128;
        pa.w[2] = wp + WV + lo; pa.lvl[2] = 32768; pa.bias[2] = cbv + l * 128;
        pa.out[2] = pv;  pa.col[2] = 0; pa.ldc[2] = 128;
        pa.w[3] = wp + WS + lo; pa.lvl[3] = 32768; pa.bias[3] = cbs + l * 128;
        pa.out[3] = out; pa.col[3] = 0; pa.ldc[3] = 128;
        mma_gemm<<<(TN + 63) / 64, 256, SM_BYTES>>>(pa, in, TN, 128, 4,
                                                    nullptr, nullptr, nullptr);

        conv_edge<<<tnwblk, 256>>>(pq, pk, pv, We, pstart, pcnt, pcsrc, pcea, out);
    }

    // ---------------- temporal attention + top-3 + output conv ----------------
    attn_outproj<<<nwblk, 256>>>(ph, aW, ab, oWq, obq, oWk, obk, oWv, obv,
                                 oWs, obs, pqs, pks, pvs, outp);
    oc_edge<<<nwblk, 256>>>(pqs, pks, pvs, oWe, pstart, pcnt, pcsrc, pcea, outp);
}

// round 12
// speedup vs baseline: 1.5087x; 1.5087x over previous
#include <cuda_runtime.h>
#include <cuda_fp16.h>
#include <math.h>
#include <stdint.h>

#define T_STEPS 8
#define NN      20000
#define FIN_DIM 32
#define EE      160000
#define HID     128
#define G3      384
#define TN      (T_STEPS * NN)
#define TE      (T_STEPS * EE)
#define SCALE   0.08838834764831845f
#define LVL_SC  2048.0f
#define LVL_INV (1.0f / 2048.0f)
#define SCAN_B  1024
#define NBLK_SCAN ((TN + SCAN_B - 1) / SCAN_B)

typedef unsigned long long u64;

// ------------------------- scratch (device globals) -------------------------
__device__ float g_h[(size_t)TN * HID];
__device__ float g_tmp[(size_t)TN * HID];
__device__ float g_q[(size_t)TN * HID];
__device__ float g_k[(size_t)TN * HID];
__device__ float g_v[(size_t)TN * HID];
__device__ float g_gi[(size_t)TN * G3];
__device__ float g_gh[(size_t)NN * G3];
__device__ float g_hprev[(size_t)NN * HID];
__device__ float g_qs[NN], g_ks[NN], g_vs[NN];
__device__ __align__(16) __half g_wprep[385024];   // 2-level fp16 split weights
// CSR
__device__ int   g_cnt[TN];
__device__ int   g_start[TN];
__device__ int   g_cur[TN];
__device__ int   g_bsum[NBLK_SCAN + 8];
__device__ int   g_csrc[TE];
__device__ float g_cea[TE];

#define WIH 0        // level stride 12288
#define WHH 24576    // level stride 49152
#define WQ  122880   // level stride 32768
#define WK  188416
#define WV  253952
#define WS  319488

// ------------------------------- helpers ------------------------------------
__device__ __forceinline__ float warp_sum(float v) {
#pragma unroll
    for (int o = 16; o; o >>= 1) v += __shfl_xor_sync(0xffffffffu, v, o);
    return v;
}
__device__ __forceinline__ float warp_max(float v) {
#pragma unroll
    for (int o = 16; o; o >>= 1) v = fmaxf(v, __shfl_xor_sync(0xffffffffu, v, o));
    return v;
}
__device__ __forceinline__ float dot4(float4 a, float4 b) {
    return a.x * b.x + a.y * b.y + a.z * b.z + a.w * b.w;
}
__device__ __forceinline__ float sigf(float x) { return 1.0f / (1.0f + expf(-x)); }

// -------- mma.sync GEMM (fp16 2-level, 3-pass; templated M-tile, N-tile 64) ---
#define ROWB 272
#define BLVL (64 * ROWB)          // 17408 B per B level (64 cols of W)

struct PArgs {
    const __half* w[4];
    int lvl[4];
    const float* bias[4];
    float* out[4];
    int col[4];
    int ldc[4];
};

__device__ __forceinline__ void mma16816(float* c, const uint32_t* a, const uint32_t* b) {
    asm volatile(
        "mma.sync.aligned.m16n8k16.row.col.f32.f16.f16.f32 "
        "{%0,%1,%2,%3},{%4,%5,%6,%7},{%8,%9},{%0,%1,%2,%3};"
        : "+f"(c[0]), "+f"(c[1]), "+f"(c[2]), "+f"(c[3])
        : "r"(a[0]), "r"(a[1]), "r"(a[2]), "r"(a[3]), "r"(b[0]), "r"(b[1]));
}
__device__ __forceinline__ void ldsm_x4(uint32_t& r0, uint32_t& r1, uint32_t& r2, uint32_t& r3,
                                        uint32_t addr) {
    asm volatile("ldmatrix.sync.aligned.m8n8.x4.shared.b16 {%0,%1,%2,%3},[%4];"
                 : "=r"(r0), "=r"(r1), "=r"(r2), "=r"(r3) : "r"(addr));
}
__device__ __forceinline__ void ldsm_x2(uint32_t& r0, uint32_t& r1, uint32_t addr) {
    asm volatile("ldmatrix.sync.aligned.m8n8.x2.shared.b16 {%0,%1},[%2];"
                 : "=r"(r0), "=r"(r1) : "r"(addr));
}
__device__ __forceinline__ uint32_t smem_addr32(const void* p) {
    return (uint32_t)__cvta_generic_to_shared(p);
}

// MT: rows per CTA (64 or 128). N-tile fixed at 64; output 128 cols per proj
// handled as 2 column-blocks with B re-staged per block.
// gi/hprev/hout non-null => fused GRU gate after the GEMM.
template<int MT, int MINB>
__global__ void __launch_bounds__(256, MINB) mma_gemm(
    PArgs pa, const float* __restrict__ A, int nrows, int K, int np,
    const float* __restrict__ gi, float* __restrict__ hprev, float* __restrict__ hout)
{
    constexpr int ALVL = MT * ROWB;
    constexpr int SB_OFF = 2 * ALVL;
    constexpr int WMW = MT / 32;          // warps along M
    constexpr int WNW = 8 / WMW;          // warps along N
    constexpr int WC  = 64 / WNW;         // cols per warp
    constexpr int NTI = WC / 8;           // 8-col frag count

    extern __shared__ char sm[];
    const uint32_t smu = smem_addr32(sm);
    const int tid = threadIdx.x, wid = tid >> 5, lane = tid & 31;
    const int brow = blockIdx.x * MT;
    const int kshift = (K == 32) ? 5 : 7;

    const int wm = (wid % WMW) * 32;
    const int wn = (wid / WMW) * WC;
    const uint32_t aoff = (uint32_t)((lane & 15) * ROWB + ((lane >> 4) & 1) * 16);
    const uint32_t boff = (uint32_t)((lane & 7) * ROWB + ((lane >> 3) & 1) * 16);

    // ---- stage A once: fp32 -> 2 fp16 levels (level 1 scaled x2048) ----
    for (int base = tid * 8; base < (MT << kshift); base += 2048) {
        const int row = base >> kshift;
        const int col = base & (K - 1);
        const int gr = brow + row;
        float4 x0 = make_float4(0.f, 0.f, 0.f, 0.f), x1 = x0;
        if (gr < nrows) {
            const float* src = A + (size_t)gr * K + col;
            x0 = *(const float4*)src;
            x1 = *(const float4*)(src + 4);
        }
        const float av[8] = {x0.x, x0.y, x0.z, x0.w, x1.x, x1.y, x1.z, x1.w};
        uint32_t p0[4], p1[4];
#pragma unroll
        for (int j = 0; j < 4; j++) {
            float a0 = av[2 * j], a1 = av[2 * j + 1];
            __half h0 = __float2half_rn(a0), h1 = __float2half_rn(a1);
            float r0 = (a0 - __half2float(h0)) * LVL_SC;
            float r1 = (a1 - __half2float(h1)) * LVL_SC;
            union { __half2 h; uint32_t u; } uh, ul;
            uh.h = __halves2half2(h0, h1);
            ul.h = __halves2half2(__float2half_rn(r0), __float2half_rn(r1));
            p0[j] = uh.u; p1[j] = ul.u;
        }
        char* dst = sm + row * ROWB + col * 2;
        *(uint4*)(dst) = make_uint4(p0[0], p0[1], p0[2], p0[3]);
        *(uint4*)(dst + ALVL) = make_uint4(p1[0], p1[1], p1[2], p1[3]);
    }

    const int nbq = (64 << kshift) >> 3;   // uint4 per B level (64 rows of W)

    for (int p = 0; p < np; p++) {
        const __half* W0 = pa.w[p];
        const int lvl = pa.lvl[p];
        float* Co = pa.out[p];
        const float* bs = pa.bias[p];
        const int ld = pa.ldc[p], cb0 = pa.col[p];

        for (int cb = 0; cb < 2; cb++) {
            __syncthreads();
            // ---- stage B half (2 levels, W rows [cb*64, cb*64+64)) ----
#pragma unroll
            for (int lv = 0; lv < 2; lv++) {
                const __half* Wl = W0 + (size_t)lv * lvl + (size_t)(cb * 64) * K;
                char* dstb = sm + SB_OFF + lv * BLVL;
                for (int i = tid; i < nbq; i += 256) {
                    const int e = i * 8;
                    const int row = e >> kshift;
                    const int col = e & (K - 1);
                    *(uint4*)(dstb + row * ROWB + col * 2) =
                        *(const uint4*)(Wl + (size_t)row * K + col);
                }
            }
            __syncthreads();

            float acc0[2][NTI][4], acc1[2][NTI][4];
#pragma unroll
            for (int i = 0; i < 2; i++)
#pragma unroll
                for (int j = 0; j < NTI; j++)
#pragma unroll
                    for (int r = 0; r < 4; r++) { acc0[i][j][r] = 0.0f; acc1[i][j][r] = 0.0f; }

            const int nk = K >> 4;
            for (int ks = 0; ks < nk; ks++) {
                const uint32_t k2 = (uint32_t)(ks << 5);
                uint32_t bf0[NTI][2], bf1[NTI][2];
                {
                    const uint32_t bb0 = smu + SB_OFF + k2 + boff;
                    const uint32_t bb1 = bb0 + BLVL;
#pragma unroll
                    for (int nt = 0; nt < NTI; nt++) {
                        ldsm_x2(bf0[nt][0], bf0[nt][1], bb0 + (uint32_t)((wn + nt * 8) * ROWB));
                        ldsm_x2(bf1[nt][0], bf1[nt][1], bb1 + (uint32_t)((wn + nt * 8) * ROWB));
                    }
                }
                uint32_t af[2][4];
                {   // A level 0: acc0 += A0*B0 ; acc1 += A0*B1'
                    const uint32_t ab = smu + k2 + aoff;
#pragma unroll
                    for (int mt = 0; mt < 2; mt++)
                        ldsm_x4(af[mt][0], af[mt][1], af[mt][2], af[mt][3],
                                ab + (uint32_t)((wm + mt * 16) * ROWB));
#pragma unroll
                    for (int mt = 0; mt < 2; mt++)
#pragma unroll
                        for (int nt = 0; nt < NTI; nt++) {
                            mma16816(acc0[mt][nt], af[mt], bf0[nt]);
                            mma16816(acc1[mt][nt], af[mt], bf1[nt]);
                        }
                }
                {   // A level 1': acc1 += A1'*B0
                    const uint32_t ab = smu + ALVL + k2 + aoff;
#pragma unroll
                    for (int mt = 0; mt < 2; mt++)
                        ldsm_x4(af[mt][0], af[mt][1], af[mt][2], af[mt][3],
                                ab + (uint32_t)((wm + mt * 16) * ROWB));
#pragma unroll
                    for (int mt = 0; mt < 2; mt++)
#pragma unroll
                        for (int nt = 0; nt < NTI; nt++)
                            mma16816(acc1[mt][nt], af[mt], bf0[nt]);
                }
            }

            // ---- epilogue: D = acc0 + acc1/2048 + bias ----
#pragma unroll
            for (int nt = 0; nt < NTI; nt++) {
                const int cloc = cb * 64 + wn + nt * 8 + (lane & 3) * 2;
                const float b0 = bs[cloc], b1 = bs[cloc + 1];
#pragma unroll
                for (int mt = 0; mt < 2; mt++) {
                    const int r0 = brow + wm + mt * 16 + (lane >> 2);
                    if (r0 < nrows) {
                        float2 o = make_float2(acc0[mt][nt][0] + acc1[mt][nt][0] * LVL_INV + b0,
                                               acc0[mt][nt][1] + acc1[mt][nt][1] * LVL_INV + b1);
                        *(float2*)(Co + (size_t)r0 * ld + cb0 + cloc) = o;
                    }
                    const int r1 = r0 + 8;
                    if (r1 < nrows) {
                        float2 o = make_float2(acc0[mt][nt][2] + acc1[mt][nt][2] * LVL_INV + b0,
                                               acc0[mt][nt][3] + acc1[mt][nt][3] * LVL_INV + b1);
                        *(float2*)(Co + (size_t)r1 * ld + cb0 + cloc) = o;
                    }
                }
            }
        }
    }

    // ---- fused GRU gate (CTA-local rows) ----
    if (gi != nullptr) {
        __syncthreads();
        const float* gh = pa.out[0];
        for (int i = tid; i < MT * 32; i += 256) {
            const int row = i >> 5;
            const int n = brow + row;
            if (n >= nrows) break;
            const int c4 = (i & 31) << 2;
            const float* gin = gi + (size_t)n * G3;
            const float* ghn = gh + (size_t)n * G3;
            float4 ir = *(const float4*)(gin + c4);
            float4 iz = *(const float4*)(gin + 128 + c4);
            float4 in_ = *(const float4*)(gin + 256 + c4);
            float4 hr = *(const float4*)(ghn + c4);
            float4 hz = *(const float4*)(ghn + 128 + c4);
            float4 hn_ = *(const float4*)(ghn + 256 + c4);
            float4 hp = *(const float4*)(hprev + (size_t)n * HID + c4);
            float4 o;
            {
                float r = sigf(ir.x + hr.x), z = sigf(iz.x + hz.x);
                float nn = tanhf(in_.x + r * hn_.x);
                o.x = (1.0f - z) * nn + z * hp.x;
            }
            {
                float r = sigf(ir.y + hr.y), z = sigf(iz.y + hz.y);
                float nn = tanhf(in_.y + r * hn_.y);
                o.y = (1.0f - z) * nn + z * hp.y;
            }
            {
                float r = sigf(ir.z + hr.z), z = sigf(iz.z + hz.z);
                float nn = tanhf(in_.z + r * hn_.z);
                o.z = (1.0f - z) * nn + z * hp.z;
            }
            {
                float r = sigf(ir.w + hr.w), z = sigf(iz.w + hz.w);
                float nn = tanhf(in_.w + r * hn_.w);
                o.w = (1.0f - z) * nn + z * hp.w;
            }
            *(float4*)(hprev + (size_t)n * HID + c4) = o;
            *(float4*)(hout + (size_t)n * HID + c4) = o;
        }
    }
}

// -------------------- merged weight prep (fp32 -> 2x fp16) -------------------
struct WPArgs { const float* src[6]; int n[6]; int base[6]; };

__global__ void wprep_all(WPArgs wa, __half* __restrict__ wp)
{
    int seg = blockIdx.y;
    int i = blockIdx.x * blockDim.x + threadIdx.x;
    if (i >= wa.n[seg]) return;
    float x = wa.src[seg][i];
    __half h = __float2half_rn(x);
    float r = (x - __half2float(h)) * LVL_SC;
    __half* w = wp + wa.base[seg];
    int n = wa.n[seg];
    w[i] = h;
    w[n + i] = __float2half_rn(r);
}

// ------------------------------- CSR build -----------------------------------
__global__ void csr_count(const int* __restrict__ ei, int* __restrict__ cnt)
{
    int w = blockIdx.x * blockDim.x + threadIdx.x;
    if (w >= TE) return;
    int t = w / EE, e = w - t * EE;
    int d = ei[(size_t)t * 2 * EE + EE + e] + t * NN;
    atomicAdd(&cnt[d], 1);
}

__global__ void __launch_bounds__(SCAN_B) scan1(
    const int* __restrict__ cnt, int* __restrict__ incl, int* __restrict__ bsum)
{
    __shared__ int sh[SCAN_B];
    int g = blockIdx.x * SCAN_B + threadIdx.x;
    int v = (g < TN) ? cnt[g] : 0;
    sh[threadIdx.x] = v;
    __syncthreads();
#pragma unroll
    for (int off = 1; off < SCAN_B; off <<= 1) {
        int add = (threadIdx.x >= off) ? sh[threadIdx.x - off] : 0;
        __syncthreads();
        sh[threadIdx.x] += add;
        __syncthreads();
    }
    if (g < TN) incl[g] = sh[threadIdx.x];
    if (threadIdx.x == SCAN_B - 1) bsum[blockIdx.x] = sh[SCAN_B - 1];
}

__global__ void __launch_bounds__(256) scan2(int* __restrict__ bsum)
{
    __shared__ int sh[256];
    int v = (threadIdx.x < NBLK_SCAN) ? bsum[threadIdx.x] : 0;
    sh[threadIdx.x] = v;
    __syncthreads();
#pragma unroll
    for (int off = 1; off < 256; off <<= 1) {
        int add = (threadIdx.x >= off) ? sh[threadIdx.x - off] : 0;
        __syncthreads();
        sh[threadIdx.x] += add;
        __syncthreads();
    }
    if (threadIdx.x < NBLK_SCAN) bsum[threadIdx.x] = sh[threadIdx.x] - v;
}

__global__ void scan3(const int* __restrict__ cnt, const int* __restrict__ incl,
                      const int* __restrict__ bsum, int* __restrict__ start,
                      int* __restrict__ cur)
{
    int g = blockIdx.x * blockDim.x + threadIdx.x;
    if (g >= TN) return;
    int s = incl[g] - cnt[g] + bsum[g / SCAN_B];
    start[g] = s;
    cur[g] = s;
}

__global__ void csr_scatter(const int* __restrict__ ei, const float* __restrict__ ea,
                            int* __restrict__ cur, int* __restrict__ csrc,
                            float* __restrict__ cea)
{
    int w = blockIdx.x * blockDim.x + threadIdx.x;
    if (w >= TE) return;
    int t = w / EE, e = w - t * EE;
    const int* eib = ei + (size_t)t * 2 * EE;
    int s = eib[e] + t * NN;
    int d = eib[EE + e] + t * NN;
    int pos = atomicAdd(&cur[d], 1);
    csrc[pos] = s;
    cea[pos] = ea[w];
}

// -------------- fused conv edge phase: warp/dst, streaming softmax -----------
__global__ void __launch_bounds__(256) conv_edge(
    const float* __restrict__ q, const float* __restrict__ k,
    const float* __restrict__ v, const float* __restrict__ We,
    const int* __restrict__ start, const int* __restrict__ cnt,
    const int* __restrict__ csrc, const float* __restrict__ cea,
    float* __restrict__ out)
{
    int n = (blockIdx.x * blockDim.x + threadIdx.x) >> 5;
    int lane = threadIdx.x & 31;
    if (n >= TN) return;
    const int i4 = lane << 2;
    float4 qv = *(const float4*)(q + (size_t)n * HID + i4);
    float4 wev = *(const float4*)(We + i4);
    float qwe = warp_sum(dot4(qv, wev)) * SCALE;

    const int s0 = start[n], c = cnt[n];
    float mx = -INFINITY, denom = 0.0f, coef = 0.0f;
    float4 macc = make_float4(0.f, 0.f, 0.f, 0.f);

    for (int j = s0; j < s0 + c; j++) {
        int s = csrc[j];
        float eav = cea[j];
        float4 kv = *(const float4*)(k + (size_t)s * HID + i4);
        float p = warp_sum(dot4(qv, kv));
        float al = p * SCALE + eav * qwe;
        float4 vv = *(const float4*)(v + (size_t)s * HID + i4);
        if (al > mx) {
            float sc = expf(mx - al);
            denom *= sc; coef *= sc;
            macc.x *= sc; macc.y *= sc; macc.z *= sc; macc.w *= sc;
            mx = al;
        }
        float a = expf(al - mx);
        denom += a;
        coef += a * eav;
        macc.x += a * vv.x; macc.y += a * vv.y; macc.z += a * vv.z; macc.w += a * vv.w;
    }

    float inv = 1.0f / (denom + 1e-16f);
    float4 sk = *(const float4*)(out + (size_t)n * HID + i4);
    float4 o;
    o.x = sk.x + (macc.x + coef * wev.x) * inv;
    o.y = sk.y + (macc.y + coef * wev.y) * inv;
    o.z = sk.z + (macc.z + coef * wev.z) * inv;
    o.w = sk.w + (macc.w + coef * wev.w) * inv;
    o.x = o.x > 0.f ? o.x : 0.01f * o.x;
    o.y = o.y > 0.f ? o.y : 0.01f * o.y;
    o.z = o.z > 0.f ? o.z : 0.01f * o.z;
    o.w = o.w > 0.f ? o.w : 0.01f * o.w;
    *(float4*)(out + (size_t)n * HID + i4) = o;
}

// ------- fused temporal attention + top-3 + output-conv projections ----------
__global__ void __launch_bounds__(256) attn_outproj(
    const float* __restrict__ h, const float* __restrict__ W,
    const float* __restrict__ b,
    const float* __restrict__ Wq, const float* __restrict__ bq,
    const float* __restrict__ Wk, const float* __restrict__ bk,
    const float* __restrict__ Wv, const float* __restrict__ bv,
    const float* __restrict__ Ws, const float* __restrict__ bs,
    float* __restrict__ qs, float* __restrict__ ks,
    float* __restrict__ vs, float* __restrict__ outp)
{
    int n = (blockIdx.x * blockDim.x + threadIdx.x) >> 5;
    int lane = threadIdx.x & 31;
    if (n >= NN) return;
    const int i4 = lane << 2;
    float4 wv = *(const float4*)(W + i4);
    float4 hv[T_STEPS];
    float s[T_STEPS];
#pragma unroll
    for (int t = 0; t < T_STEPS; t++) {
        hv[t] = *(const float4*)(h + ((size_t)t * NN + n) * HID + i4);
        s[t] = warp_sum(dot4(hv[t], wv)) + b[0];
    }
    float mx = s[0];
#pragma unroll
    for (int t = 1; t < T_STEPS; t++) mx = fmaxf(mx, s[t]);
    float aw[T_STEPS]; float tot = 0.0f;
#pragma unroll
    for (int t = 0; t < T_STEPS; t++) { aw[t] = expf(s[t] - mx); tot += aw[t]; }
    float inv = 1.0f / tot;
#pragma unroll
    for (int t = 0; t < T_STEPS; t++) aw[t] *= inv;
    bool sel[T_STEPS];
#pragma unroll
    for (int t = 0; t < T_STEPS; t++) sel[t] = false;
    float sum3 = 0.0f;
#pragma unroll
    for (int r = 0; r < 3; r++) {
        float best = -1.0f; int bi = 0;
#pragma unroll
        for (int t = 0; t < T_STEPS; t++)
            if (!sel[t] && aw[t] > best) { best = aw[t]; bi = t; }
        sel[bi] = true; sum3 += best;
    }
    float winv = 1.0f / (sum3 + 1e-8f);
    float4 acc = make_float4(0.f, 0.f, 0.f, 0.f);
#pragma unroll
    for (int t = 0; t < T_STEPS; t++) {
        float w = sel[t] ? aw[t] * winv : 0.0f;
        acc.x += w * hv[t].x; acc.y += w * hv[t].y;
        acc.z += w * hv[t].z; acc.w += w * hv[t].w;
    }
    float4 wq = *(const float4*)(Wq + i4);
    float4 wk = *(const float4*)(Wk + i4);
    float4 wvv = *(const float4*)(Wv + i4);
    float4 ws = *(const float4*)(Ws + i4);
    float pq = warp_sum(dot4(acc, wq));
    float pk = warp_sum(dot4(acc, wk));
    float pv = warp_sum(dot4(acc, wvv));
    float ps = warp_sum(dot4(acc, ws));
    if (lane == 0) {
        qs[n] = pq + bq[0];
        ks[n] = pk + bk[0];
        vs[n] = pv + bv[0];
        outp[n] = ps + bs[0];
    }
}

// fused output-conv edge phase (warp/dst, lanes over edges, reuses t=7 CSR)
__global__ void __launch_bounds__(256) oc_edge(
    const float* __restrict__ qs, const float* __restrict__ ks,
    const float* __restrict__ vs, const float* __restrict__ We,
    const int* __restrict__ start, const int* __restrict__ cnt,
    const int* __restrict__ csrc, const float* __restrict__ cea,
    float* __restrict__ outp)
{
    int n = (blockIdx.x * blockDim.x + threadIdx.x) >> 5;
    int lane = threadIdx.x & 31;
    if (n >= NN) return;
    const int g = (T_STEPS - 1) * NN + n;
    const int s0 = start[g], c = cnt[g];
    if (c == 0) return;
    const float qsn = qs[n];
    const float we0 = We[0];

    float mx = -INFINITY;
    for (int j = s0 + lane; j < s0 + c; j += 32) {
        int sl = csrc[j] - (T_STEPS - 1) * NN;
        float al = qsn * (ks[sl] + cea[j] * we0);
        mx = fmaxf(mx, al);
    }
    mx = warp_max(mx);

    float dsum = 0.f, msum = 0.f;
    for (int j = s0 + lane; j < s0 + c; j += 32) {
        int sl = csrc[j] - (T_STEPS - 1) * NN;
        float eav = cea[j];
        float al = qsn * (ks[sl] + eav * we0);
        float a = expf(al - mx);
        dsum += a;
        msum += a * (vs[sl] + eav * we0);
    }
    dsum = warp_sum(dsum);
    msum = warp_sum(msum);
    if (lane == 0) outp[n] += msum / (dsum + 1e-16f);
}

// --------------------------------- host --------------------------------------
static float* symf(const void* sym) { void* p = nullptr; cudaGetSymbolAddress(&p, sym); return (float*)p; }

extern "C" void kernel_launch(void* const* d_in, const int* in_sizes, int n_in,
                              void* d_out, int out_size)
{
    const float* x_seq = (const float*)d_in[0];
    const int*   ei    = (const int*)d_in[1];
    const float* ea    = (const float*)d_in[2];
    const float* W_ih  = (const float*)d_in[3];
    const float* W_hh  = (const float*)d_in[4];
    const float* b_ih  = (const float*)d_in[5];
    const float* b_hh  = (const float*)d_in[6];
    const float* cWq = (const float*)d_in[7];  const float* cbq = (const float*)d_in[8];
    const float* cWk = (const float*)d_in[9];  const float* cbk = (const float*)d_in[10];
    const float* cWv = (const float*)d_in[11]; const float* cbv = (const float*)d_in[12];
    const float* cWe = (const float*)d_in[13];
    const float* cWs = (const float*)d_in[14]; const float* cbs = (const float*)d_in[15];
    const float* oWq = (const float*)d_in[16]; const float* obq = (const float*)d_in[17];
    const float* oWk = (const float*)d_in[18]; const float* obk = (const float*)d_in[19];
    const float* oWv = (const float*)d_in[20]; const float* obv = (const float*)d_in[21];
    const float* oWe = (const float*)d_in[22];
    const float* oWs = (const float*)d_in[23]; const float* obs = (const float*)d_in[24];
    const float* aW  = (const float*)d_in[25]; const float* ab  = (const float*)d_in[26];
    float* outp = (float*)d_out;

    float* ph     = symf(g_h);
    float* ptmp   = symf(g_tmp);
    float* pq     = symf(g_q);
    float* pk     = symf(g_k);
    float* pv     = symf(g_v);
    float* pgi    = symf(g_gi);
    float* pgh    = symf(g_gh);
    float* phprev = symf(g_hprev);
    float* pqs    = symf(g_qs);
    float* pks    = symf(g_ks);
    float* pvs    = symf(g_vs);
    int*   pcnt   = (int*)symf(g_cnt);
    int*   pstart = (int*)symf(g_start);
    int*   pcur   = (int*)symf(g_cur);
    int*   pbsum  = (int*)symf(g_bsum);
    int*   pcsrc  = (int*)symf(g_csrc);
    float* pcea   = symf(g_cea);
    __half* wp    = (__half*)symf(g_wprep);

    const int SM128 = 2 * 128 * ROWB + 2 * BLVL;   // 104448
    const int SM64  = 2 * 64 * ROWB + 2 * BLVL;    // 69632
    cudaFuncSetAttribute(mma_gemm<128, 2>, cudaFuncAttributeMaxDynamicSharedMemorySize, SM128);
    cudaFuncSetAttribute(mma_gemm<64, 3>,  cudaFuncAttributeMaxDynamicSharedMemorySize, SM64);

    const int nwblk  = (NN + 7) / 8;
    const int tnwblk = (TN + 7) / 8;
    const int teblk  = (TE + 255) / 256;
    const int tnblk  = (TN + 255) / 256;

    // ---------------- weight prep ----------------
    {
        WPArgs wa;
        wa.src[0] = W_ih; wa.n[0] = 12288; wa.base[0] = WIH;
        wa.src[1] = W_hh; wa.n[1] = 49152; wa.base[1] = WHH;
        wa.src[2] = cWq;  wa.n[2] = 32768; wa.base[2] = WQ;
        wa.src[3] = cWk;  wa.n[3] = 32768; wa.base[3] = WK;
        wa.src[4] = cWv;  wa.n[4] = 32768; wa.base[4] = WV;
        wa.src[5] = cWs;  wa.n[5] = 32768; wa.base[5] = WS;
        wprep_all<<<dim3((49152 + 255) / 256, 6), 256>>>(wa, wp);
    }

    // ---------------- GRU ----------------
    cudaMemsetAsync(phprev, 0, (size_t)NN * HID * sizeof(float));
    {
        PArgs pa;
        for (int p = 0; p < 3; p++) {
            pa.w[p] = wp + WIH + (size_t)p * 128 * 32;
            pa.lvl[p] = 12288;
            pa.bias[p] = b_ih + p * 128;
            pa.out[p] = pgi; pa.col[p] = p * 128; pa.ldc[p] = G3;
        }
        pa.w[3] = pa.w[2]; pa.lvl[3] = 12288; pa.bias[3] = pa.bias[2];
        pa.out[3] = pgi; pa.col[3] = 256; pa.ldc[3] = G3;
        mma_gemm<128, 2><<<(TN + 127) / 128, 256, SM128>>>(pa, x_seq, TN, 32, 3,
                                                           nullptr, nullptr, nullptr);
    }
    {
        PArgs pa;
        for (int p = 0; p < 3; p++) {
            pa.w[p] = wp + WHH + (size_t)p * 128 * 128;
            pa.lvl[p] = 49152;
            pa.bias[p] = b_hh + p * 128;
            pa.out[p] = pgh; pa.col[p] = p * 128; pa.ldc[p] = G3;
        }
        pa.w[3] = pa.w[2]; pa.lvl[3] = 49152; pa.bias[3] = pa.bias[2];
        pa.out[3] = pgh; pa.col[3] = 256; pa.ldc[3] = G3;
        for (int t = 0; t < T_STEPS; t++) {
            mma_gemm<64, 3><<<(NN + 63) / 64, 256, SM64>>>(
                pa, phprev, NN, 128, 3,
                pgi + (size_t)t * NN * G3, phprev, ph + (size_t)t * NN * HID);
        }
    }

    // ---------------- CSR build ----------------
    cudaMemsetAsync(pcnt, 0, TN * sizeof(int));
    csr_count<<<teblk, 256>>>(ei, pcnt);
    scan1<<<NBLK_SCAN, SCAN_B>>>(pcnt, pcur, pbsum);
    scan2<<<1, 256>>>(pbsum);
    scan3<<<tnblk, 256>>>(pcnt, pcur, pbsum, pstart, pcur);
    csr_scatter<<<teblk, 256>>>(ei, ea, pcur, pcsrc, pcea);

    // ---------------- GNN: 2 layers, batched over all T ----------------
    for (int l = 0; l < 2; l++) {
        const float* in  = (l == 0) ? ph : ptmp;
        float*       out = (l == 0) ? ptmp : ph;
        const float* We = cWe + (size_t)l * HID;
        size_t lo = (size_t)l * 16384;

        PArgs pa;
        pa.w[0] = wp + WQ + lo; pa.lvl[0] = 32768; pa.bias[0] = cbq + l * 128;
        pa.out[0] = pq;  pa.col[0] = 0; pa.ldc[0] = 128;
        pa.w[1] = wp + WK + lo; pa.lvl[1] = 32768; pa.bias[1] = cbk + l * 128;
        pa.out[1] = pk;  pa.col[1] = 0; pa.ldc[1] = 128;
        pa.w[2] = wp + WV + lo; pa.lvl[2] = 32768; pa.bias[2] = cbv + l * 128;
        pa.out[2] = pv;  pa.col[2] = 0; pa.ldc[2] = 128;
        pa.w[3] = wp + WS + lo; pa.lvl[3] = 32768; pa.bias[3] = cbs + l * 128;
        pa.out[3] = out; pa.col[3] = 0; pa.ldc[3] = 128;
        mma_gemm<128, 2><<<(TN + 127) / 128, 256, SM128>>>(pa, in, TN, 128, 4,
                                                           nullptr, nullptr, nullptr);

        conv_edge<<<tnwblk, 256>>>(pq, pk, pv, We, pstart, pcnt, pcsrc, pcea, out);
    }

    // ---------------- temporal attention + top-3 + output conv ----------------
    attn_outproj<<<nwblk, 256>>>(ph, aW, ab, oWq, obq, oWk, obk, oWv, obv,
                                 oWs, obs, pqs, pks, pvs, outp);
    oc_edge<<<nwblk, 256>>>(pqs, pks, pvs, oWe, pstart, pcnt, pcsrc, pcea, outp);
}

// round 13
// speedup vs baseline: 1.5199x; 1.0075x over previous
#include <cuda_runtime.h>
#include <cuda_fp16.h>
#include <math.h>
#include <stdint.h>

#define T_STEPS 8
#define NN      20000
#define FIN_DIM 32
#define EE      160000
#define HID     128
#define G3      384
#define TN      (T_STEPS * NN)
#define TE      (T_STEPS * EE)
#define SCALE   0.08838834764831845f
#define LVL_SC  2048.0f
#define LVL_INV (1.0f / 2048.0f)
#define SCAN_B  1024
#define NBLK_SCAN ((TN + SCAN_B - 1) / SCAN_B)

typedef unsigned long long u64;

// ------------------------- scratch (device globals) -------------------------
__device__ float g_h[(size_t)TN * HID];
__device__ float g_tmp[(size_t)TN * HID];
__device__ float g_q[(size_t)TN * HID];
__device__ float g_k[(size_t)TN * HID];
__device__ float g_v[(size_t)TN * HID];
__device__ float g_gi[(size_t)TN * G3];
__device__ float g_gh[(size_t)NN * G3];
__device__ float g_hprev[(size_t)NN * HID];
__device__ float g_qs[NN], g_ks[NN], g_vs[NN];
__device__ __align__(16) __half g_wprep[385024];   // 2-level fp16 split weights
// CSR
__device__ int   g_cnt[TN];
__device__ int   g_start[TN];
__device__ int   g_cur[TN];
__device__ int   g_bsum[NBLK_SCAN + 8];
__device__ int   g_csrc[TE];
__device__ float g_cea[TE];

#define WIH 0        // level stride 12288
#define WHH 24576    // level stride 49152
#define WQ  122880   // level stride 32768
#define WK  188416
#define WV  253952
#define WS  319488

// ------------------------------- helpers ------------------------------------
__device__ __forceinline__ float warp_sum(float v) {
#pragma unroll
    for (int o = 16; o; o >>= 1) v += __shfl_xor_sync(0xffffffffu, v, o);
    return v;
}
__device__ __forceinline__ float warp_max(float v) {
#pragma unroll
    for (int o = 16; o; o >>= 1) v = fmaxf(v, __shfl_xor_sync(0xffffffffu, v, o));
    return v;
}
__device__ __forceinline__ float dot4(float4 a, float4 b) {
    return a.x * b.x + a.y * b.y + a.z * b.z + a.w * b.w;
}
__device__ __forceinline__ float sigf(float x) { return 1.0f / (1.0f + __expf(-x)); }

// -------- mma.sync GEMM (fp16 2-level, 3-pass; templated M-tile, N-tile 64) ---
#define ROWB 272
#define BLVL (64 * ROWB)          // 17408 B per B level (64 cols of W)

struct PArgs {
    const __half* w[4];
    int lvl[4];
    const float* bias[4];
    float* out[4];
    int col[4];
    int ldc[4];
};

__device__ __forceinline__ void mma16816(float* c, const uint32_t* a, const uint32_t* b) {
    asm volatile(
        "mma.sync.aligned.m16n8k16.row.col.f32.f16.f16.f32 "
        "{%0,%1,%2,%3},{%4,%5,%6,%7},{%8,%9},{%0,%1,%2,%3};"
        : "+f"(c[0]), "+f"(c[1]), "+f"(c[2]), "+f"(c[3])
        : "r"(a[0]), "r"(a[1]), "r"(a[2]), "r"(a[3]), "r"(b[0]), "r"(b[1]));
}
__device__ __forceinline__ void ldsm_x4(uint32_t& r0, uint32_t& r1, uint32_t& r2, uint32_t& r3,
                                        uint32_t addr) {
    asm volatile("ldmatrix.sync.aligned.m8n8.x4.shared.b16 {%0,%1,%2,%3},[%4];"
                 : "=r"(r0), "=r"(r1), "=r"(r2), "=r"(r3) : "r"(addr));
}
__device__ __forceinline__ void ldsm_x2(uint32_t& r0, uint32_t& r1, uint32_t addr) {
    asm volatile("ldmatrix.sync.aligned.m8n8.x2.shared.b16 {%0,%1},[%2];"
                 : "=r"(r0), "=r"(r1) : "r"(addr));
}
__device__ __forceinline__ uint32_t smem_addr32(const void* p) {
    return (uint32_t)__cvta_generic_to_shared(p);
}

// MT: rows per CTA (64 or 128). N-tile fixed at 64; 128-col outputs handled as
// 2 column-blocks with B re-staged per block. gi != null => fused GRU gate.
template<int MT, int MINB>
__global__ void __launch_bounds__(256, MINB) mma_gemm(
    PArgs pa, const float* __restrict__ A, int nrows, int K, int np,
    const float* __restrict__ gi, float* __restrict__ hprev, float* __restrict__ hout)
{
    constexpr int ALVL = MT * ROWB;
    constexpr int SB_OFF = 2 * ALVL;
    constexpr int WMW = MT / 32;
    constexpr int WNW = 8 / WMW;
    constexpr int WC  = 64 / WNW;
    constexpr int NTI = WC / 8;

    extern __shared__ char sm[];
    const uint32_t smu = smem_addr32(sm);
    const int tid = threadIdx.x, wid = tid >> 5, lane = tid & 31;
    const int brow = blockIdx.x * MT;
    const int kshift = (K == 32) ? 5 : 7;

    const int wm = (wid % WMW) * 32;
    const int wn = (wid / WMW) * WC;
    const uint32_t aoff = (uint32_t)((lane & 15) * ROWB + ((lane >> 4) & 1) * 16);
    const uint32_t boff = (uint32_t)((lane & 7) * ROWB + ((lane >> 3) & 1) * 16);

    // ---- stage A once: fp32 -> 2 fp16 levels (level 1 scaled x2048) ----
    for (int base = tid * 8; base < (MT << kshift); base += 2048) {
        const int row = base >> kshift;
        const int col = base & (K - 1);
        const int gr = brow + row;
        float4 x0 = make_float4(0.f, 0.f, 0.f, 0.f), x1 = x0;
        if (gr < nrows) {
            const float* src = A + (size_t)gr * K + col;
            x0 = *(const float4*)src;
            x1 = *(const float4*)(src + 4);
        }
        const float av[8] = {x0.x, x0.y, x0.z, x0.w, x1.x, x1.y, x1.z, x1.w};
        uint32_t p0[4], p1[4];
#pragma unroll
        for (int j = 0; j < 4; j++) {
            float a0 = av[2 * j], a1 = av[2 * j + 1];
            __half h0 = __float2half_rn(a0), h1 = __float2half_rn(a1);
            float r0 = (a0 - __half2float(h0)) * LVL_SC;
            float r1 = (a1 - __half2float(h1)) * LVL_SC;
            union { __half2 h; uint32_t u; } uh, ul;
            uh.h = __halves2half2(h0, h1);
            ul.h = __halves2half2(__float2half_rn(r0), __float2half_rn(r1));
            p0[j] = uh.u; p1[j] = ul.u;
        }
        char* dst = sm + row * ROWB + col * 2;
        *(uint4*)(dst) = make_uint4(p0[0], p0[1], p0[2], p0[3]);
        *(uint4*)(dst + ALVL) = make_uint4(p1[0], p1[1], p1[2], p1[3]);
    }

    const int nbq = (64 << kshift) >> 3;

    for (int p = 0; p < np; p++) {
        const __half* W0 = pa.w[p];
        const int lvl = pa.lvl[p];
        float* Co = pa.out[p];
        const float* bs = pa.bias[p];
        const int ld = pa.ldc[p], cb0 = pa.col[p];

        for (int cb = 0; cb < 2; cb++) {
            __syncthreads();
#pragma unroll
            for (int lv = 0; lv < 2; lv++) {
                const __half* Wl = W0 + (size_t)lv * lvl + (size_t)(cb * 64) * K;
                char* dstb = sm + SB_OFF + lv * BLVL;
                for (int i = tid; i < nbq; i += 256) {
                    const int e = i * 8;
                    const int row = e >> kshift;
                    const int col = e & (K - 1);
                    *(uint4*)(dstb + row * ROWB + col * 2) =
                        *(const uint4*)(Wl + (size_t)row * K + col);
                }
            }
            __syncthreads();

            float acc0[2][NTI][4], acc1[2][NTI][4];
#pragma unroll
            for (int i = 0; i < 2; i++)
#pragma unroll
                for (int j = 0; j < NTI; j++)
#pragma unroll
                    for (int r = 0; r < 4; r++) { acc0[i][j][r] = 0.0f; acc1[i][j][r] = 0.0f; }

            const int nk = K >> 4;
            for (int ks = 0; ks < nk; ks++) {
                const uint32_t k2 = (uint32_t)(ks << 5);
                uint32_t bf0[NTI][2], bf1[NTI][2];
                {
                    const uint32_t bb0 = smu + SB_OFF + k2 + boff;
                    const uint32_t bb1 = bb0 + BLVL;
#pragma unroll
                    for (int nt = 0; nt < NTI; nt++) {
                        ldsm_x2(bf0[nt][0], bf0[nt][1], bb0 + (uint32_t)((wn + nt * 8) * ROWB));
                        ldsm_x2(bf1[nt][0], bf1[nt][1], bb1 + (uint32_t)((wn + nt * 8) * ROWB));
                    }
                }
                uint32_t af[2][4];
                {
                    const uint32_t ab = smu + k2 + aoff;
#pragma unroll
                    for (int mt = 0; mt < 2; mt++)
                        ldsm_x4(af[mt][0], af[mt][1], af[mt][2], af[mt][3],
                                ab + (uint32_t)((wm + mt * 16) * ROWB));
#pragma unroll
                    for (int mt = 0; mt < 2; mt++)
#pragma unroll
                        for (int nt = 0; nt < NTI; nt++) {
                            mma16816(acc0[mt][nt], af[mt], bf0[nt]);
                            mma16816(acc1[mt][nt], af[mt], bf1[nt]);
                        }
                }
                {
                    const uint32_t ab = smu + ALVL + k2 + aoff;
#pragma unroll
                    for (int mt = 0; mt < 2; mt++)
                        ldsm_x4(af[mt][0], af[mt][1], af[mt][2], af[mt][3],
                                ab + (uint32_t)((wm + mt * 16) * ROWB));
#pragma unroll
                    for (int mt = 0; mt < 2; mt++)
#pragma unroll
                        for (int nt = 0; nt < NTI; nt++)
                            mma16816(acc1[mt][nt], af[mt], bf0[nt]);
                }
            }

#pragma unroll
            for (int nt = 0; nt < NTI; nt++) {
                const int cloc = cb * 64 + wn + nt * 8 + (lane & 3) * 2;
                const float b0 = bs[cloc], b1 = bs[cloc + 1];
#pragma unroll
                for (int mt = 0; mt < 2; mt++) {
                    const int r0 = brow + wm + mt * 16 + (lane >> 2);
                    if (r0 < nrows) {
                        float2 o = make_float2(acc0[mt][nt][0] + acc1[mt][nt][0] * LVL_INV + b0,
                                               acc0[mt][nt][1] + acc1[mt][nt][1] * LVL_INV + b1);
                        *(float2*)(Co + (size_t)r0 * ld + cb0 + cloc) = o;
                    }
                    const int r1 = r0 + 8;
                    if (r1 < nrows) {
                        float2 o = make_float2(acc0[mt][nt][2] + acc1[mt][nt][2] * LVL_INV + b0,
                                               acc0[mt][nt][3] + acc1[mt][nt][3] * LVL_INV + b1);
                        *(float2*)(Co + (size_t)r1 * ld + cb0 + cloc) = o;
                    }
                }
            }
        }
    }

    // ---- fused GRU gate (CTA-local rows) ----
    if (gi != nullptr) {
        __syncthreads();
        const float* gh = pa.out[0];
        for (int i = tid; i < MT * 32; i += 256) {
            const int row = i >> 5;
            const int n = brow + row;
            if (n >= nrows) break;
            const int c4 = (i & 31) << 2;
            const float* gin = gi + (size_t)n * G3;
            const float* ghn = gh + (size_t)n * G3;
            float4 ir = *(const float4*)(gin + c4);
            float4 iz = *(const float4*)(gin + 128 + c4);
            float4 in_ = *(const float4*)(gin + 256 + c4);
            float4 hr = *(const float4*)(ghn + c4);
            float4 hz = *(const float4*)(ghn + 128 + c4);
            float4 hn_ = *(const float4*)(ghn + 256 + c4);
            float4 hp = *(const float4*)(hprev + (size_t)n * HID + c4);
            float4 o;
            {
                float r = sigf(ir.x + hr.x), z = sigf(iz.x + hz.x);
                float nn = tanhf(in_.x + r * hn_.x);
                o.x = (1.0f - z) * nn + z * hp.x;
            }
            {
                float r = sigf(ir.y + hr.y), z = sigf(iz.y + hz.y);
                float nn = tanhf(in_.y + r * hn_.y);
                o.y = (1.0f - z) * nn + z * hp.y;
            }
            {
                float r = sigf(ir.z + hr.z), z = sigf(iz.z + hz.z);
                float nn = tanhf(in_.z + r * hn_.z);
                o.z = (1.0f - z) * nn + z * hp.z;
            }
            {
                float r = sigf(ir.w + hr.w), z = sigf(iz.w + hz.w);
                float nn = tanhf(in_.w + r * hn_.w);
                o.w = (1.0f - z) * nn + z * hp.w;
            }
            *(float4*)(hprev + (size_t)n * HID + c4) = o;
            *(float4*)(hout + (size_t)n * HID + c4) = o;
        }
    }
}

// -------------------- merged weight prep (fp32 -> 2x fp16) -------------------
struct WPArgs { const float* src[6]; int n[6]; int base[6]; };

__global__ void wprep_all(WPArgs wa, __half* __restrict__ wp)
{
    int seg = blockIdx.y;
    int i = blockIdx.x * blockDim.x + threadIdx.x;
    if (i >= wa.n[seg]) return;
    float x = wa.src[seg][i];
    __half h = __float2half_rn(x);
    float r = (x - __half2float(h)) * LVL_SC;
    __half* w = wp + wa.base[seg];
    int n = wa.n[seg];
    w[i] = h;
    w[n + i] = __float2half_rn(r);
}

// ------------------------------- CSR build -----------------------------------
__global__ void csr_count(const int* __restrict__ ei, int* __restrict__ cnt)
{
    int w = blockIdx.x * blockDim.x + threadIdx.x;
    if (w >= TE) return;
    int t = w / EE, e = w - t * EE;
    int d = ei[(size_t)t * 2 * EE + EE + e] + t * NN;
    atomicAdd(&cnt[d], 1);
}

__global__ void __launch_bounds__(SCAN_B) scan1(
    const int* __restrict__ cnt, int* __restrict__ incl, int* __restrict__ bsum)
{
    __shared__ int sh[SCAN_B];
    int g = blockIdx.x * SCAN_B + threadIdx.x;
    int v = (g < TN) ? cnt[g] : 0;
    sh[threadIdx.x] = v;
    __syncthreads();
#pragma unroll
    for (int off = 1; off < SCAN_B; off <<= 1) {
        int add = (threadIdx.x >= off) ? sh[threadIdx.x - off] : 0;
        __syncthreads();
        sh[threadIdx.x] += add;
        __syncthreads();
    }
    if (g < TN) incl[g] = sh[threadIdx.x];
    if (threadIdx.x == SCAN_B - 1) bsum[blockIdx.x] = sh[SCAN_B - 1];
}

__global__ void __launch_bounds__(256) scan2(int* __restrict__ bsum)
{
    __shared__ int sh[256];
    int v = (threadIdx.x < NBLK_SCAN) ? bsum[threadIdx.x] : 0;
    sh[threadIdx.x] = v;
    __syncthreads();
#pragma unroll
    for (int off = 1; off < 256; off <<= 1) {
        int add = (threadIdx.x >= off) ? sh[threadIdx.x - off] : 0;
        __syncthreads();
        sh[threadIdx.x] += add;
        __syncthreads();
    }
    if (threadIdx.x < NBLK_SCAN) bsum[threadIdx.x] = sh[threadIdx.x] - v;
}

__global__ void scan3(const int* __restrict__ cnt, const int* __restrict__ incl,
                      const int* __restrict__ bsum, int* __restrict__ start,
                      int* __restrict__ cur)
{
    int g = blockIdx.x * blockDim.x + threadIdx.x;
    if (g >= TN) return;
    int s = incl[g] - cnt[g] + bsum[g / SCAN_B];
    start[g] = s;
    cur[g] = s;
}

__global__ void csr_scatter(const int* __restrict__ ei, const float* __restrict__ ea,
                            int* __restrict__ cur, int* __restrict__ csrc,
                            float* __restrict__ cea)
{
    int w = blockIdx.x * blockDim.x + threadIdx.x;
    if (w >= TE) return;
    int t = w / EE, e = w - t * EE;
    const int* eib = ei + (size_t)t * 2 * EE;
    int s = eib[e] + t * NN;
    int d = eib[EE + e] + t * NN;
    int pos = atomicAdd(&cur[d], 1);
    csrc[pos] = s;
    cea[pos] = ea[w];
}

// ---- fused conv edge phase: warp/dst, streaming softmax, pipelined gathers ---
__global__ void __launch_bounds__(256) conv_edge(
    const float* __restrict__ q, const float* __restrict__ k,
    const float* __restrict__ v, const float* __restrict__ We,
    const int* __restrict__ start, const int* __restrict__ cnt,
    const int* __restrict__ csrc, const float* __restrict__ cea,
    float* __restrict__ out)
{
    int n = (blockIdx.x * blockDim.x + threadIdx.x) >> 5;
    int lane = threadIdx.x & 31;
    if (n >= TN) return;
    const int i4 = lane << 2;
    float4 qv = *(const float4*)(q + (size_t)n * HID + i4);
    float4 wev = *(const float4*)(We + i4);
    float qwe = warp_sum(dot4(qv, wev)) * SCALE;

    const int s0 = start[n], c = cnt[n];
    float mx = -INFINITY, denom = 0.0f, coef = 0.0f;
    float4 macc = make_float4(0.f, 0.f, 0.f, 0.f);

    if (c > 0) {
        // prefetch edge s0
        int s = csrc[s0];
        float eav = cea[s0];
        float4 kv = *(const float4*)(k + (size_t)s * HID + i4);
        float4 vv = *(const float4*)(v + (size_t)s * HID + i4);

        for (int j = s0; j < s0 + c; j++) {
            float4 kv_c = kv, vv_c = vv;
            float eav_c = eav;
            if (j + 1 < s0 + c) {                // issue next gathers early
                int sn = csrc[j + 1];
                eav = cea[j + 1];
                kv = *(const float4*)(k + (size_t)sn * HID + i4);
                vv = *(const float4*)(v + (size_t)sn * HID + i4);
            }
            float p = warp_sum(dot4(qv, kv_c));
            float al = p * SCALE + eav_c * qwe;
            if (al > mx) {
                float sc = __expf(mx - al);
                denom *= sc; coef *= sc;
                macc.x *= sc; macc.y *= sc; macc.z *= sc; macc.w *= sc;
                mx = al;
            }
            float a = __expf(al - mx);
            denom += a;
            coef += a * eav_c;
            macc.x += a * vv_c.x; macc.y += a * vv_c.y;
            macc.z += a * vv_c.z; macc.w += a * vv_c.w;
        }
    }

    float inv = 1.0f / (denom + 1e-16f);
    float4 sk = *(const float4*)(out + (size_t)n * HID + i4);
    float4 o;
    o.x = sk.x + (macc.x + coef * wev.x) * inv;
    o.y = sk.y + (macc.y + coef * wev.y) * inv;
    o.z = sk.z + (macc.z + coef * wev.z) * inv;
    o.w = sk.w + (macc.w + coef * wev.w) * inv;
    o.x = o.x > 0.f ? o.x : 0.01f * o.x;
    o.y = o.y > 0.f ? o.y : 0.01f * o.y;
    o.z = o.z > 0.f ? o.z : 0.01f * o.z;
    o.w = o.w > 0.f ? o.w : 0.01f * o.w;
    *(float4*)(out + (size_t)n * HID + i4) = o;
}

// ------- fused temporal attention + top-3 + output-conv projections ----------
__global__ void __launch_bounds__(256) attn_outproj(
    const float* __restrict__ h, const float* __restrict__ W,
    const float* __restrict__ b,
    const float* __restrict__ Wq, const float* __restrict__ bq,
    const float* __restrict__ Wk, const float* __restrict__ bk,
    const float* __restrict__ Wv, const float* __restrict__ bv,
    const float* __restrict__ Ws, const float* __restrict__ bs,
    float* __restrict__ qs, float* __restrict__ ks,
    float* __restrict__ vs, float* __restrict__ outp)
{
    int n = (blockIdx.x * blockDim.x + threadIdx.x) >> 5;
    int lane = threadIdx.x & 31;
    if (n >= NN) return;
    const int i4 = lane << 2;
    float4 wv = *(const float4*)(W + i4);
    float4 hv[T_STEPS];
    float s[T_STEPS];
#pragma unroll
    for (int t = 0; t < T_STEPS; t++) {
        hv[t] = *(const float4*)(h + ((size_t)t * NN + n) * HID + i4);
        s[t] = warp_sum(dot4(hv[t], wv)) + b[0];
    }
    float mx = s[0];
#pragma unroll
    for (int t = 1; t < T_STEPS; t++) mx = fmaxf(mx, s[t]);
    float aw[T_STEPS]; float tot = 0.0f;
#pragma unroll
    for (int t = 0; t < T_STEPS; t++) { aw[t] = __expf(s[t] - mx); tot += aw[t]; }
    float inv = 1.0f / tot;
#pragma unroll
    for (int t = 0; t < T_STEPS; t++) aw[t] *= inv;
    bool sel[T_STEPS];
#pragma unroll
    for (int t = 0; t < T_STEPS; t++) sel[t] = false;
    float sum3 = 0.0f;
#pragma unroll
    for (int r = 0; r < 3; r++) {
        float best = -1.0f; int bi = 0;
#pragma unroll
        for (int t = 0; t < T_STEPS; t++)
            if (!sel[t] && aw[t] > best) { best = aw[t]; bi = t; }
        sel[bi] = true; sum3 += best;
    }
    float winv = 1.0f / (sum3 + 1e-8f);
    float4 acc = make_float4(0.f, 0.f, 0.f, 0.f);
#pragma unroll
    for (int t = 0; t < T_STEPS; t++) {
        float w = sel[t] ? aw[t] * winv : 0.0f;
        acc.x += w * hv[t].x; acc.y += w * hv[t].y;
        acc.z += w * hv[t].z; acc.w += w * hv[t].w;
    }
    float4 wq = *(const float4*)(Wq + i4);
    float4 wk = *(const float4*)(Wk + i4);
    float4 wvv = *(const float4*)(Wv + i4);
    float4 ws = *(const float4*)(Ws + i4);
    float pq = warp_sum(dot4(acc, wq));
    float pk = warp_sum(dot4(acc, wk));
    float pv = warp_sum(dot4(acc, wvv));
    float ps = warp_sum(dot4(acc, ws));
    if (lane == 0) {
        qs[n] = pq + bq[0];
        ks[n] = pk + bk[0];
        vs[n] = pv + bv[0];
        outp[n] = ps + bs[0];
    }
}

// fused output-conv edge phase (warp/dst, lanes over edges, reuses t=7 CSR)
__global__ void __launch_bounds__(256) oc_edge(
    const float* __restrict__ qs, const float* __restrict__ ks,
    const float* __restrict__ vs, const float* __restrict__ We,
    const int* __restrict__ start, const int* __restrict__ cnt,
    const int* __restrict__ csrc, const float* __restrict__ cea,
    float* __restrict__ outp)
{
    int n = (blockIdx.x * blockDim.x + threadIdx.x) >> 5;
    int lane = threadIdx.x & 31;
    if (n >= NN) return;
    const int g = (T_STEPS - 1) * NN + n;
    const int s0 = start[g], c = cnt[g];
    if (c == 0) return;
    const float qsn = qs[n];
    const float we0 = We[0];

    float mx = -INFINITY;
    for (int j = s0 + lane; j < s0 + c; j += 32) {
        int sl = csrc[j] - (T_STEPS - 1) * NN;
        float al = qsn * (ks[sl] + cea[j] * we0);
        mx = fmaxf(mx, al);
    }
    mx = warp_max(mx);

    float dsum = 0.f, msum = 0.f;
    for (int j = s0 + lane; j < s0 + c; j += 32) {
        int sl = csrc[j] - (T_STEPS - 1) * NN;
        float eav = cea[j];
        float al = qsn * (ks[sl] + eav * we0);
        float a = __expf(al - mx);
        dsum += a;
        msum += a * (vs[sl] + eav * we0);
    }
    dsum = warp_sum(dsum);
    msum = warp_sum(msum);
    if (lane == 0) outp[n] += msum / (dsum + 1e-16f);
}

// --------------------------------- host --------------------------------------
static float* symf(const void* sym) { void* p = nullptr; cudaGetSymbolAddress(&p, sym); return (float*)p; }

extern "C" void kernel_launch(void* const* d_in, const int* in_sizes, int n_in,
                              void* d_out, int out_size)
{
    const float* x_seq = (const float*)d_in[0];
    const int*   ei    = (const int*)d_in[1];
    const float* ea    = (const float*)d_in[2];
    const float* W_ih  = (const float*)d_in[3];
    const float* W_hh  = (const float*)d_in[4];
    const float* b_ih  = (const float*)d_in[5];
    const float* b_hh  = (const float*)d_in[6];
    const float* cWq = (const float*)d_in[7];  const float* cbq = (const float*)d_in[8];
    const float* cWk = (const float*)d_in[9];  const float* cbk = (const float*)d_in[10];
    const float* cWv = (const float*)d_in[11]; const float* cbv = (const float*)d_in[12];
    const float* cWe = (const float*)d_in[13];
    const float* cWs = (const float*)d_in[14]; const float* cbs = (const float*)d_in[15];
    const float* oWq = (const float*)d_in[16]; const float* obq = (const float*)d_in[17];
    const float* oWk = (const float*)d_in[18]; const float* obk = (const float*)d_in[19];
    const float* oWv = (const float*)d_in[20]; const float* obv = (const float*)d_in[21];
    const float* oWe = (const float*)d_in[22];
    const float* oWs = (const float*)d_in[23]; const float* obs = (const float*)d_in[24];
    const float* aW  = (const float*)d_in[25]; const float* ab  = (const float*)d_in[26];
    float* outp = (float*)d_out;

    float* ph     = symf(g_h);
    float* ptmp   = symf(g_tmp);
    float* pq     = symf(g_q);
    float* pk     = symf(g_k);
    float* pv     = symf(g_v);
    float* pgi    = symf(g_gi);
    float* pgh    = symf(g_gh);
    float* phprev = symf(g_hprev);
    float* pqs    = symf(g_qs);
    float* pks    = symf(g_ks);
    float* pvs    = symf(g_vs);
    int*   pcnt   = (int*)symf(g_cnt);
    int*   pstart = (int*)symf(g_start);
    int*   pcur   = (int*)symf(g_cur);
    int*   pbsum  = (int*)symf(g_bsum);
    int*   pcsrc  = (int*)symf(g_csrc);
    float* pcea   = symf(g_cea);
    __half* wp    = (__half*)symf(g_wprep);

    const int SM128 = 2 * 128 * ROWB + 2 * BLVL;   // 104448
    const int SM64  = 2 * 64 * ROWB + 2 * BLVL;    // 69632
    cudaFuncSetAttribute(mma_gemm<128, 2>, cudaFuncAttributeMaxDynamicSharedMemorySize, SM128);
    cudaFuncSetAttribute(mma_gemm<64, 3>,  cudaFuncAttributeMaxDynamicSharedMemorySize, SM64);

    const int nwblk  = (NN + 7) / 8;
    const int tnwblk = (TN + 7) / 8;
    const int teblk  = (TE + 255) / 256;
    const int tnblk  = (TN + 255) / 256;

    // ---------------- weight prep ----------------
    {
        WPArgs wa;
        wa.src[0] = W_ih; wa.n[0] = 12288; wa.base[0] = WIH;
        wa.src[1] = W_hh; wa.n[1] = 49152; wa.base[1] = WHH;
        wa.src[2] = cWq;  wa.n[2] = 32768; wa.base[2] = WQ;
        wa.src[3] = cWk;  wa.n[3] = 32768; wa.base[3] = WK;
        wa.src[4] = cWv;  wa.n[4] = 32768; wa.base[4] = WV;
        wa.src[5] = cWs;  wa.n[5] = 32768; wa.base[5] = WS;
        wprep_all<<<dim3((49152 + 255) / 256, 6), 256>>>(wa, wp);
    }

    // ---------------- GRU ----------------
    cudaMemsetAsync(phprev, 0, (size_t)NN * HID * sizeof(float));
    {
        PArgs pa;
        for (int p = 0; p < 3; p++) {
            pa.w[p] = wp + WIH + (size_t)p * 128 * 32;
            pa.lvl[p] = 12288;
            pa.bias[p] = b_ih + p * 128;
            pa.out[p] = pgi; pa.col[p] = p * 128; pa.ldc[p] = G3;
        }
        pa.w[3] = pa.w[2]; pa.lvl[3] = 12288; pa.bias[3] = pa.bias[2];
        pa.out[3] = pgi; pa.col[3] = 256; pa.ldc[3] = G3;
        mma_gemm<128, 2><<<(TN + 127) / 128, 256, SM128>>>(pa, x_seq, TN, 32, 3,
                                                           nullptr, nullptr, nullptr);
    }
    {
        PArgs pa;
        for (int p = 0; p < 3; p++) {
            pa.w[p] = wp + WHH + (size_t)p * 128 * 128;
            pa.lvl[p] = 49152;
            pa.bias[p] = b_hh + p * 128;
            pa.out[p] = pgh; pa.col[p] = p * 128; pa.ldc[p] = G3;
        }
        pa.w[3] = pa.w[2]; pa.lvl[3] = 49152; pa.bias[3] = pa.bias[2];
        pa.out[3] = pgh; pa.col[3] = 256; pa.ldc[3] = G3;
        for (int t = 0; t < T_STEPS; t++) {
            mma_gemm<64, 3><<<(NN + 63) / 64, 256, SM64>>>(
                pa, phprev, NN, 128, 3,
                pgi + (size_t)t * NN * G3, phprev, ph + (size_t)t * NN * HID);
        }
    }

    // ---------------- CSR build ----------------
    cudaMemsetAsync(pcnt, 0, TN * sizeof(int));
    csr_count<<<teblk, 256>>>(ei, pcnt);
    scan1<<<NBLK_SCAN, SCAN_B>>>(pcnt, pcur, pbsum);
    scan2<<<1, 256>>>(pbsum);
    scan3<<<tnblk, 256>>>(pcnt, pcur, pbsum, pstart, pcur);
    csr_scatter<<<teblk, 256>>>(ei, ea, pcur, pcsrc, pcea);

    // ---------------- GNN: 2 layers, batched over all T ----------------
    for (int l = 0; l < 2; l++) {
        const float* in  = (l == 0) ? ph : ptmp;
        float*       out = (l == 0) ? ptmp : ph;
        const float* We = cWe + (size_t)l * HID;
        size_t lo = (size_t)l * 16384;

        PArgs pa;
        pa.w[0] = wp + WQ + lo; pa.lvl[0] = 32768; pa.bias[0] = cbq + l * 128;
        pa.out[0] = pq;  pa.col[0] = 0; pa.ldc[0] = 128;
        pa.w[1] = wp + WK + lo; pa.lvl[1] = 32768; pa.bias[1] = cbk + l * 128;
        pa.out[1] = pk;  pa.col[1] = 0; pa.ldc[1] = 128;
        pa.w[2] = wp + WV + lo; pa.lvl[2] = 32768; pa.bias[2] = cbv + l * 128;
        pa.out[2] = pv;  pa.col[2] = 0; pa.ldc[2] = 128;
        pa.w[3] = wp + WS + lo; pa.lvl[3] = 32768; pa.bias[3] = cbs + l * 128;
        pa.out[3] = out; pa.col[3] = 0; pa.ldc[3] = 128;
        mma_gemm<128, 2><<<(TN + 127) / 128, 256, SM128>>>(pa, in, TN, 128, 4,
                                                           nullptr, nullptr, nullptr);

        conv_edge<<<tnwblk, 256>>>(pq, pk, pv, We, pstart, pcnt, pcsrc, pcea, out);
    }

    // ---------------- temporal attention + top-3 + output conv ----------------
    attn_outproj<<<nwblk, 256>>>(ph, aW, ab, oWq, obq, oWk, obk, oWv, obv,
                                 oWs, obs, pqs, pks, pvs, outp);
    oc_edge<<<nwblk, 256>>>(pqs, pks, pvs, oWe, pstart, pcnt, pcsrc, pcea, outp);
}

// round 17
// speedup vs baseline: 1.5519x; 1.0210x over previous
#include <cuda_runtime.h>
#include <cuda_fp16.h>
#include <math.h>
#include <stdint.h>

#define T_STEPS 8
#define NN      20000
#define FIN_DIM 32
#define EE      160000
#define HID     128
#define G3      384
#define TN      (T_STEPS * NN)
#define TE      (T_STEPS * EE)
#define SCALE   0.08838834764831845f
#define LVL_SC  2048.0f
#define LVL_INV (1.0f / 2048.0f)
#define SCAN_B  1024
#define NBLK_SCAN ((TN + SCAN_B - 1) / SCAN_B)

typedef unsigned long long u64;

// ------------------------- scratch (device globals) -------------------------
__device__ float g_h[(size_t)TN * HID];
__device__ float g_tmp[(size_t)TN * HID];
__device__ float g_q[(size_t)TN * HID];
__device__ float g_k[(size_t)TN * HID];
__device__ float g_v[(size_t)TN * HID];
__device__ float g_gi[(size_t)TN * G3];
__device__ float g_gh[(size_t)NN * G3];
__device__ float g_hprev[(size_t)NN * HID];
__device__ float g_qs[NN], g_ks[NN], g_vs[NN];
__device__ __align__(16) __half g_wprep[385024];   // 2-level fp16 split weights
// CSR
__device__ int   g_cnt[TN];
__device__ int   g_start[TN];
__device__ int   g_cur[TN];
__device__ int   g_bsum[NBLK_SCAN + 8];
__device__ int   g_csrc[TE];
__device__ float g_cea[TE];

#define WIH 0        // level stride 12288
#define WHH 24576    // level stride 49152
#define WQ  122880   // level stride 32768
#define WK  188416
#define WV  253952
#define WS  319488

// ------------------------------- helpers ------------------------------------
__device__ __forceinline__ float warp_sum(float v) {
#pragma unroll
    for (int o = 16; o; o >>= 1) v += __shfl_xor_sync(0xffffffffu, v, o);
    return v;
}
__device__ __forceinline__ float warp_max(float v) {
#pragma unroll
    for (int o = 16; o; o >>= 1) v = fmaxf(v, __shfl_xor_sync(0xffffffffu, v, o));
    return v;
}
__device__ __forceinline__ float dot4(float4 a, float4 b) {
    return a.x * b.x + a.y * b.y + a.z * b.z + a.w * b.w;
}
__device__ __forceinline__ float sigf(float x) { return 1.0f / (1.0f + __expf(-x)); }

// -------- mma.sync GEMM (fp16 2-level, 3-pass; templated M-tile, N-tile 64) ---
#define ROWB 272
#define BLVL (64 * ROWB)          // 17408 B per B level (64 cols of W)

struct PArgs {
    const __half* w[4];
    int lvl[4];
    const float* bias[4];
    float* out[4];
    int col[4];
    int ldc[4];
};

__device__ __forceinline__ void mma16816(float* c, const uint32_t* a, const uint32_t* b) {
    asm volatile(
        "mma.sync.aligned.m16n8k16.row.col.f32.f16.f16.f32 "
        "{%0,%1,%2,%3},{%4,%5,%6,%7},{%8,%9},{%0,%1,%2,%3};"
        : "+f"(c[0]), "+f"(c[1]), "+f"(c[2]), "+f"(c[3])
        : "r"(a[0]), "r"(a[1]), "r"(a[2]), "r"(a[3]), "r"(b[0]), "r"(b[1]));
}
__device__ __forceinline__ void ldsm_x4(uint32_t& r0, uint32_t& r1, uint32_t& r2, uint32_t& r3,
                                        uint32_t addr) {
    asm volatile("ldmatrix.sync.aligned.m8n8.x4.shared.b16 {%0,%1,%2,%3},[%4];"
                 : "=r"(r0), "=r"(r1), "=r"(r2), "=r"(r3) : "r"(addr));
}
__device__ __forceinline__ void ldsm_x2(uint32_t& r0, uint32_t& r1, uint32_t addr) {
    asm volatile("ldmatrix.sync.aligned.m8n8.x2.shared.b16 {%0,%1},[%2];"
                 : "=r"(r0), "=r"(r1) : "r"(addr));
}
__device__ __forceinline__ uint32_t smem_addr32(const void* p) {
    return (uint32_t)__cvta_generic_to_shared(p);
}

// MT: rows per CTA (64 or 128). N-tile fixed at 64; 128-col outputs handled as
// 2 column-blocks with B re-staged per block. gi != null => fused GRU gate.
template<int MT, int MINB>
__global__ void __launch_bounds__(256, MINB) mma_gemm(
    PArgs pa, const float* __restrict__ A, int nrows, int K, int np,
    const float* __restrict__ gi, float* __restrict__ hprev, float* __restrict__ hout)
{
    constexpr int ALVL = MT * ROWB;
    constexpr int SB_OFF = 2 * ALVL;
    constexpr int WMW = MT / 32;
    constexpr int WNW = 8 / WMW;
    constexpr int WC  = 64 / WNW;
    constexpr int NTI = WC / 8;

    extern __shared__ char sm[];
    const uint32_t smu = smem_addr32(sm);
    const int tid = threadIdx.x, wid = tid >> 5, lane = tid & 31;
    const int brow = blockIdx.x * MT;
    const int kshift = (K == 32) ? 5 : 7;

    const int wm = (wid % WMW) * 32;
    const int wn = (wid / WMW) * WC;
    const uint32_t aoff = (uint32_t)((lane & 15) * ROWB + ((lane >> 4) & 1) * 16);
    const uint32_t boff = (uint32_t)((lane & 7) * ROWB + ((lane >> 3) & 1) * 16);

    // ---- stage A once: fp32 -> 2 fp16 levels (level 1 scaled x2048) ----
    for (int base = tid * 8; base < (MT << kshift); base += 2048) {
        const int row = base >> kshift;
        const int col = base & (K - 1);
        const int gr = brow + row;
        float4 x0 = make_float4(0.f, 0.f, 0.f, 0.f), x1 = x0;
        if (gr < nrows) {
            const float* src = A + (size_t)gr * K + col;
            x0 = *(const float4*)src;
            x1 = *(const float4*)(src + 4);
        }
        const float av[8] = {x0.x, x0.y, x0.z, x0.w, x1.x, x1.y, x1.z, x1.w};
        uint32_t p0[4], p1[4];
#pragma unroll
        for (int j = 0; j < 4; j++) {
            float a0 = av[2 * j], a1 = av[2 * j + 1];
            __half h0 = __float2half_rn(a0), h1 = __float2half_rn(a1);
            float r0 = (a0 - __half2float(h0)) * LVL_SC;
            float r1 = (a1 - __half2float(h1)) * LVL_SC;
            union { __half2 h; uint32_t u; } uh, ul;
            uh.h = __halves2half2(h0, h1);
            ul.h = __halves2half2(__float2half_rn(r0), __float2half_rn(r1));
            p0[j] = uh.u; p1[j] = ul.u;
        }
        char* dst = sm + row * ROWB + col * 2;
        *(uint4*)(dst) = make_uint4(p0[0], p0[1], p0[2], p0[3]);
        *(uint4*)(dst + ALVL) = make_uint4(p1[0], p1[1], p1[2], p1[3]);
    }

    const int nbq = (64 << kshift) >> 3;

    for (int p = 0; p < np; p++) {
        const __half* W0 = pa.w[p];
        const int lvl = pa.lvl[p];
        float* Co = pa.out[p];
        const float* bs = pa.bias[p];
        const int ld = pa.ldc[p], cb0 = pa.col[p];

        for (int cb = 0; cb < 2; cb++) {
            __syncthreads();
#pragma unroll
            for (int lv = 0; lv < 2; lv++) {
                const __half* Wl = W0 + (size_t)lv * lvl + (size_t)(cb * 64) * K;
                char* dstb = sm + SB_OFF + lv * BLVL;
                for (int i = tid; i < nbq; i += 256) {
                    const int e = i * 8;
                    const int row = e >> kshift;
                    const int col = e & (K - 1);
                    *(uint4*)(dstb + row * ROWB + col * 2) =
                        *(const uint4*)(Wl + (size_t)row * K + col);
                }
            }
            __syncthreads();

            float acc0[2][NTI][4], acc1[2][NTI][4];
#pragma unroll
            for (int i = 0; i < 2; i++)
#pragma unroll
                for (int j = 0; j < NTI; j++)
#pragma unroll
                    for (int r = 0; r < 4; r++) { acc0[i][j][r] = 0.0f; acc1[i][j][r] = 0.0f; }

            const int nk = K >> 4;
            for (int ks = 0; ks < nk; ks++) {
                const uint32_t k2 = (uint32_t)(ks << 5);
                uint32_t bf0[NTI][2], bf1[NTI][2];
                {
                    const uint32_t bb0 = smu + SB_OFF + k2 + boff;
                    const uint32_t bb1 = bb0 + BLVL;
#pragma unroll
                    for (int nt = 0; nt < NTI; nt++) {
                        ldsm_x2(bf0[nt][0], bf0[nt][1], bb0 + (uint32_t)((wn + nt * 8) * ROWB));
                        ldsm_x2(bf1[nt][0], bf1[nt][1], bb1 + (uint32_t)((wn + nt * 8) * ROWB));
                    }
                }
                uint32_t af[2][4];
                {
                    const uint32_t ab = smu + k2 + aoff;
#pragma unroll
                    for (int mt = 0; mt < 2; mt++)
                        ldsm_x4(af[mt][0], af[mt][1], af[mt][2], af[mt][3],
                                ab + (uint32_t)((wm + mt * 16) * ROWB));
#pragma unroll
                    for (int mt = 0; mt < 2; mt++)
#pragma unroll
                        for (int nt = 0; nt < NTI; nt++) {
                            mma16816(acc0[mt][nt], af[mt], bf0[nt]);
                            mma16816(acc1[mt][nt], af[mt], bf1[nt]);
                        }
                }
                {
                    const uint32_t ab = smu + ALVL + k2 + aoff;
#pragma unroll
                    for (int mt = 0; mt < 2; mt++)
                        ldsm_x4(af[mt][0], af[mt][1], af[mt][2], af[mt][3],
                                ab + (uint32_t)((wm + mt * 16) * ROWB));
#pragma unroll
                    for (int mt = 0; mt < 2; mt++)
#pragma unroll
                        for (int nt = 0; nt < NTI; nt++)
                            mma16816(acc1[mt][nt], af[mt], bf0[nt]);
                }
            }

#pragma unroll
            for (int nt = 0; nt < NTI; nt++) {
                const int cloc = cb * 64 + wn + nt * 8 + (lane & 3) * 2;
                const float b0 = bs[cloc], b1 = bs[cloc + 1];
#pragma unroll
                for (int mt = 0; mt < 2; mt++) {
                    const int r0 = brow + wm + mt * 16 + (lane >> 2);
                    if (r0 < nrows) {
                        float2 o = make_float2(acc0[mt][nt][0] + acc1[mt][nt][0] * LVL_INV + b0,
                                               acc0[mt][nt][1] + acc1[mt][nt][1] * LVL_INV + b1);
                        *(float2*)(Co + (size_t)r0 * ld + cb0 + cloc) = o;
                    }
                    const int r1 = r0 + 8;
                    if (r1 < nrows) {
                        float2 o = make_float2(acc0[mt][nt][2] + acc1[mt][nt][2] * LVL_INV + b0,
                                               acc0[mt][nt][3] + acc1[mt][nt][3] * LVL_INV + b1);
                        *(float2*)(Co + (size_t)r1 * ld + cb0 + cloc) = o;
                    }
                }
            }
        }
    }

    // ---- fused GRU gate (CTA-local rows) ----
    if (gi != nullptr) {
        __syncthreads();
        const float* gh = pa.out[0];
        for (int i = tid; i < MT * 32; i += 256) {
            const int row = i >> 5;
            const int n = brow + row;
            if (n >= nrows) break;
            const int c4 = (i & 31) << 2;
            const float* gin = gi + (size_t)n * G3;
            const float* ghn = gh + (size_t)n * G3;
            float4 ir = *(const float4*)(gin + c4);
            float4 iz = *(const float4*)(gin + 128 + c4);
            float4 in_ = *(const float4*)(gin + 256 + c4);
            float4 hr = *(const float4*)(ghn + c4);
            float4 hz = *(const float4*)(ghn + 128 + c4);
            float4 hn_ = *(const float4*)(ghn + 256 + c4);
            float4 hp = *(const float4*)(hprev + (size_t)n * HID + c4);
            float4 o;
            {
                float r = sigf(ir.x + hr.x), z = sigf(iz.x + hz.x);
                float nn = tanhf(in_.x + r * hn_.x);
                o.x = (1.0f - z) * nn + z * hp.x;
            }
            {
                float r = sigf(ir.y + hr.y), z = sigf(iz.y + hz.y);
                float nn = tanhf(in_.y + r * hn_.y);
                o.y = (1.0f - z) * nn + z * hp.y;
            }
            {
                float r = sigf(ir.z + hr.z), z = sigf(iz.z + hz.z);
                float nn = tanhf(in_.z + r * hn_.z);
                o.z = (1.0f - z) * nn + z * hp.z;
            }
            {
                float r = sigf(ir.w + hr.w), z = sigf(iz.w + hz.w);
                float nn = tanhf(in_.w + r * hn_.w);
                o.w = (1.0f - z) * nn + z * hp.w;
            }
            *(float4*)(hprev + (size_t)n * HID + c4) = o;
            *(float4*)(hout + (size_t)n * HID + c4) = o;
        }
    }
}

// -------------------- merged weight prep (fp32 -> 2x fp16) -------------------
struct WPArgs { const float* src[6]; int n[6]; int base[6]; };

__global__ void wprep_all(WPArgs wa, __half* __restrict__ wp)
{
    int seg = blockIdx.y;
    int i = blockIdx.x * blockDim.x + threadIdx.x;
    if (i >= wa.n[seg]) return;
    float x = wa.src[seg][i];
    __half h = __float2half_rn(x);
    float r = (x - __half2float(h)) * LVL_SC;
    __half* w = wp + wa.base[seg];
    int n = wa.n[seg];
    w[i] = h;
    w[n + i] = __float2half_rn(r);
}

// ------------------------------- CSR build -----------------------------------
__global__ void csr_count(const int* __restrict__ ei, int* __restrict__ cnt)
{
    int w = blockIdx.x * blockDim.x + threadIdx.x;
    if (w >= TE) return;
    int t = w / EE, e = w - t * EE;
    int d = ei[(size_t)t * 2 * EE + EE + e] + t * NN;
    atomicAdd(&cnt[d], 1);
}

__global__ void __launch_bounds__(SCAN_B) scan1(
    const int* __restrict__ cnt, int* __restrict__ incl, int* __restrict__ bsum)
{
    __shared__ int sh[SCAN_B];
    int g = blockIdx.x * SCAN_B + threadIdx.x;
    int v = (g < TN) ? cnt[g] : 0;
    sh[threadIdx.x] = v;
    __syncthreads();
#pragma unroll
    for (int off = 1; off < SCAN_B; off <<= 1) {
        int add = (threadIdx.x >= off) ? sh[threadIdx.x - off] : 0;
        __syncthreads();
        sh[threadIdx.x] += add;
        __syncthreads();
    }
    if (g < TN) incl[g] = sh[threadIdx.x];
    if (threadIdx.x == SCAN_B - 1) bsum[blockIdx.x] = sh[SCAN_B - 1];
}

__global__ void __launch_bounds__(256) scan2(int* __restrict__ bsum)
{
    __shared__ int sh[256];
    int v = (threadIdx.x < NBLK_SCAN) ? bsum[threadIdx.x] : 0;
    sh[threadIdx.x] = v;
    __syncthreads();
#pragma unroll
    for (int off = 1; off < 256; off <<= 1) {
        int add = (threadIdx.x >= off) ? sh[threadIdx.x - off] : 0;
        __syncthreads();
        sh[threadIdx.x] += add;
        __syncthreads();
    }
    if (threadIdx.x < NBLK_SCAN) bsum[threadIdx.x] = sh[threadIdx.x] - v;
}

__global__ void scan3(const int* __restrict__ cnt, const int* __restrict__ incl,
                      const int* __restrict__ bsum, int* __restrict__ start,
                      int* __restrict__ cur)
{
    int g = blockIdx.x * blockDim.x + threadIdx.x;
    if (g >= TN) return;
    int s = incl[g] - cnt[g] + bsum[g / SCAN_B];
    start[g] = s;
    cur[g] = s;
}

__global__ void csr_scatter(const int* __restrict__ ei, const float* __restrict__ ea,
                            int* __restrict__ cur, int* __restrict__ csrc,
                            float* __restrict__ cea)
{
    int w = blockIdx.x * blockDim.x + threadIdx.x;
    if (w >= TE) return;
    int t = w / EE, e = w - t * EE;
    const int* eib = ei + (size_t)t * 2 * EE;
    int s = eib[e] + t * NN;
    int d = eib[EE + e] + t * NN;
    int pos = atomicAdd(&cur[d], 1);
    csrc[pos] = s;
    cea[pos] = ea[w];
}

// ---- fused conv edge phase: warp/dst, streaming softmax, 2-edge unroll -------
// Two edges per iteration: dots + paired shuffle reductions issue together
// (independent chains), then softmax updates apply IN ORIGINAL EDGE ORDER, so
// the arithmetic is bit-identical to the serial version.
__global__ void __launch_bounds__(256) conv_edge(
    const float* __restrict__ q, const float* __restrict__ k,
    const float* __restrict__ v, const float* __restrict__ We,
    const int* __restrict__ start, const int* __restrict__ cnt,
    const int* __restrict__ csrc, const float* __restrict__ cea,
    float* __restrict__ out)
{
    int n = (blockIdx.x * blockDim.x + threadIdx.x) >> 5;
    int lane = threadIdx.x & 31;
    if (n >= TN) return;
    const int i4 = lane << 2;
    float4 qv = *(const float4*)(q + (size_t)n * HID + i4);
    float4 wev = *(const float4*)(We + i4);
    float qwe = warp_sum(dot4(qv, wev)) * SCALE;

    const int s0 = start[n], c = cnt[n];
    const int eend = s0 + c;
    float mx = -INFINITY, denom = 0.0f, coef = 0.0f;
    float4 macc = make_float4(0.f, 0.f, 0.f, 0.f);

    int j = s0;
    for (; j + 1 < eend; j += 2) {
        int sa = csrc[j], sb = csrc[j + 1];
        float ea0 = cea[j], ea1 = cea[j + 1];
        float4 kva = *(const float4*)(k + (size_t)sa * HID + i4);
        float4 kvb = *(const float4*)(k + (size_t)sb * HID + i4);
        float4 vva = *(const float4*)(v + (size_t)sa * HID + i4);
        float4 vvb = *(const float4*)(v + (size_t)sb * HID + i4);
        float p0 = dot4(qv, kva);
        float p1 = dot4(qv, kvb);
#pragma unroll
        for (int o = 16; o; o >>= 1) {
            p0 += __shfl_xor_sync(0xffffffffu, p0, o);
            p1 += __shfl_xor_sync(0xffffffffu, p1, o);
        }
        float al0 = p0 * SCALE + ea0 * qwe;
        float al1 = p1 * SCALE + ea1 * qwe;
        // update edge j (original order)
        if (al0 > mx) {
            float sc = __expf(mx - al0);
            denom *= sc; coef *= sc;
            macc.x *= sc; macc.y *= sc; macc.z *= sc; macc.w *= sc;
            mx = al0;
        }
        {
            float a = __expf(al0 - mx);
            denom += a; coef += a * ea0;
            macc.x += a * vva.x; macc.y += a * vva.y;
            macc.z += a * vva.z; macc.w += a * vva.w;
        }
        // update edge j+1
        if (al1 > mx) {
            float sc = __expf(mx - al1);
            denom *= sc; coef *= sc;
            macc.x *= sc; macc.y *= sc; macc.z *= sc; macc.w *= sc;
            mx = al1;
        }
        {
            float a = __expf(al1 - mx);
            denom += a; coef += a * ea1;
            macc.x += a * vvb.x; macc.y += a * vvb.y;
            macc.z += a * vvb.z; macc.w += a * vvb.w;
        }
    }
    if (j < eend) {   // leftover edge
        int sa = csrc[j];
        float ea0 = cea[j];
        float4 kva = *(const float4*)(k + (size_t)sa * HID + i4);
        float4 vva = *(const float4*)(v + (size_t)sa * HID + i4);
        float p0 = warp_sum(dot4(qv, kva));
        float al0 = p0 * SCALE + ea0 * qwe;
        if (al0 > mx) {
            float sc = __expf(mx - al0);
            denom *= sc; coef *= sc;
            macc.x *= sc; macc.y *= sc; macc.z *= sc; macc.w *= sc;
            mx = al0;
        }
        float a = __expf(al0 - mx);
        denom += a; coef += a * ea0;
        macc.x += a * vva.x; macc.y += a * vva.y;
        macc.z += a * vva.z; macc.w += a * vva.w;
    }

    float inv = 1.0f / (denom + 1e-16f);
    float4 sk = *(const float4*)(out + (size_t)n * HID + i4);
    float4 o;
    o.x = sk.x + (macc.x + coef * wev.x) * inv;
    o.y = sk.y + (macc.y + coef * wev.y) * inv;
    o.z = sk.z + (macc.z + coef * wev.z) * inv;
    o.w = sk.w + (macc.w + coef * wev.w) * inv;
    o.x = o.x > 0.f ? o.x : 0.01f * o.x;
    o.y = o.y > 0.f ? o.y : 0.01f * o.y;
    o.z = o.z > 0.f ? o.z : 0.01f * o.z;
    o.w = o.w > 0.f ? o.w : 0.01f * o.w;
    *(float4*)(out + (size_t)n * HID + i4) = o;
}

// ------- fused temporal attention + top-3 + output-conv projections ----------
__global__ void __launch_bounds__(256) attn_outproj(
    const float* __restrict__ h, const float* __restrict__ W,
    const float* __restrict__ b,
    const float* __restrict__ Wq, const float* __restrict__ bq,
    const float* __restrict__ Wk, const float* __restrict__ bk,
    const float* __restrict__ Wv, const float* __restrict__ bv,
    const float* __restrict__ Ws, const float* __restrict__ bs,
    float* __restrict__ qs, float* __restrict__ ks,
    float* __restrict__ vs, float* __restrict__ outp)
{
    int n = (blockIdx.x * blockDim.x + threadIdx.x) >> 5;
    int lane = threadIdx.x & 31;
    if (n >= NN) return;
    const int i4 = lane << 2;
    float4 wv = *(const float4*)(W + i4);
    float4 hv[T_STEPS];
    float s[T_STEPS];
#pragma unroll
    for (int t = 0; t < T_STEPS; t++) {
        hv[t] = *(const float4*)(h + ((size_t)t * NN + n) * HID + i4);
        s[t] = warp_sum(dot4(hv[t], wv)) + b[0];
    }
    float mx = s[0];
#pragma unroll
    for (int t = 1; t < T_STEPS; t++) mx = fmaxf(mx, s[t]);
    float aw[T_STEPS]; float tot = 0.0f;
#pragma unroll
    for (int t = 0; t < T_STEPS; t++) { aw[t] = __expf(s[t] - mx); tot += aw[t]; }
    float inv = 1.0f / tot;
#pragma unroll
    for (int t = 0; t < T_STEPS; t++) aw[t] *= inv;
    bool sel[T_STEPS];
#pragma unroll
    for (int t = 0; t < T_STEPS; t++) sel[t] = false;
    float sum3 = 0.0f;
#pragma unroll
    for (int r = 0; r < 3; r++) {
        float best = -1.0f; int bi = 0;
#pragma unroll
        for (int t = 0; t < T_STEPS; t++)
            if (!sel[t] && aw[t] > best) { best = aw[t]; bi = t; }
        sel[bi] = true; sum3 += best;
    }
    float winv = 1.0f / (sum3 + 1e-8f);
    float4 acc = make_float4(0.f, 0.f, 0.f, 0.f);
#pragma unroll
    for (int t = 0; t < T_STEPS; t++) {
        float w = sel[t] ? aw[t] * winv : 0.0f;
        acc.x += w * hv[t].x; acc.y += w * hv[t].y;
        acc.z += w * hv[t].z; acc.w += w * hv[t].w;
    }
    float4 wq = *(const float4*)(Wq + i4);
    float4 wk = *(const float4*)(Wk + i4);
    float4 wvv = *(const float4*)(Wv + i4);
    float4 ws = *(const float4*)(Ws + i4);
    float pq = warp_sum(dot4(acc, wq));
    float pk = warp_sum(dot4(acc, wk));
    float pv = warp_sum(dot4(acc, wvv));
    float ps = warp_sum(dot4(acc, ws));
    if (lane == 0) {
        qs[n] = pq + bq[0];
        ks[n] = pk + bk[0];
        vs[n] = pv + bv[0];
        outp[n] = ps + bs[0];
    }
}

// fused output-conv edge phase (warp/dst, lanes over edges, reuses t=7 CSR)
__global__ void __launch_bounds__(256) oc_edge(
    const float* __restrict__ qs, const float* __restrict__ ks,
    const float* __restrict__ vs, const float* __restrict__ We,
    const int* __restrict__ start, const int* __restrict__ cnt,
    const int* __restrict__ csrc, const float* __restrict__ cea,
    float* __restrict__ outp)
{
    int n = (blockIdx.x * blockDim.x + threadIdx.x) >> 5;
    int lane = threadIdx.x & 31;
    if (n >= NN) return;
    const int g = (T_STEPS - 1) * NN + n;
    const int s0 = start[g], c = cnt[g];
    if (c == 0) return;
    const float qsn = qs[n];
    const float we0 = We[0];

    float mx = -INFINITY;
    for (int j = s0 + lane; j < s0 + c; j += 32) {
        int sl = csrc[j] - (T_STEPS - 1) * NN;
        float al = qsn * (ks[sl] + cea[j] * we0);
        mx = fmaxf(mx, al);
    }
    mx = warp_max(mx);

    float dsum = 0.f, msum = 0.f;
    for (int j = s0 + lane; j < s0 + c; j += 32) {
        int sl = csrc[j] - (T_STEPS - 1) * NN;
        float eav = cea[j];
        float al = qsn * (ks[sl] + eav * we0);
        float a = __expf(al - mx);
        dsum += a;
        msum += a * (vs[sl] + eav * we0);
    }
    dsum = warp_sum(dsum);
    msum = warp_sum(msum);
    if (lane == 0) outp[n] += msum / (dsum + 1e-16f);
}

// --------------------------------- host --------------------------------------
static float* symf(const void* sym) { void* p = nullptr; cudaGetSymbolAddress(&p, sym); return (float*)p; }

extern "C" void kernel_launch(void* const* d_in, const int* in_sizes, int n_in,
                              void* d_out, int out_size)
{
    const float* x_seq = (const float*)d_in[0];
    const int*   ei    = (const int*)d_in[1];
    const float* ea    = (const float*)d_in[2];
    const float* W_ih  = (const float*)d_in[3];
    const float* W_hh  = (const float*)d_in[4];
    const float* b_ih  = (const float*)d_in[5];
    const float* b_hh  = (const float*)d_in[6];
    const float* cWq = (const float*)d_in[7];  const float* cbq = (const float*)d_in[8];
    const float* cWk = (const float*)d_in[9];  const float* cbk = (const float*)d_in[10];
    const float* cWv = (const float*)d_in[11]; const float* cbv = (const float*)d_in[12];
    const float* cWe = (const float*)d_in[13];
    const float* cWs = (const float*)d_in[14]; const float* cbs = (const float*)d_in[15];
    const float* oWq = (const float*)d_in[16]; const float* obq = (const float*)d_in[17];
    const float* oWk = (const float*)d_in[18]; const float* obk = (const float*)d_in[19];
    const float* oWv = (const float*)d_in[20]; const float* obv = (const float*)d_in[21];
    const float* oWe = (const float*)d_in[22];
    const float* oWs = (const float*)d_in[23]; const float* obs = (const float*)d_in[24];
    const float* aW  = (const float*)d_in[25]; const float* ab  = (const float*)d_in[26];
    float* outp = (float*)d_out;

    float* ph     = symf(g_h);
    float* ptmp   = symf(g_tmp);
    float* pq     = symf(g_q);
    float* pk     = symf(g_k);
    float* pv     = symf(g_v);
    float* pgi    = symf(g_gi);
    float* pgh    = symf(g_gh);
    float* phprev = symf(g_hprev);
    float* pqs    = symf(g_qs);
    float* pks    = symf(g_ks);
    float* pvs    = symf(g_vs);
    int*   pcnt   = (int*)symf(g_cnt);
    int*   pstart = (int*)symf(g_start);
    int*   pcur   = (int*)symf(g_cur);
    int*   pbsum  = (int*)symf(g_bsum);
    int*   pcsrc  = (int*)symf(g_csrc);
    float* pcea   = symf(g_cea);
    __half* wp    = (__half*)symf(g_wprep);

    const int SM128 = 2 * 128 * ROWB + 2 * BLVL;   // 104448
    const int SM64  = 2 * 64 * ROWB + 2 * BLVL;    // 69632
    cudaFuncSetAttribute(mma_gemm<128, 2>, cudaFuncAttributeMaxDynamicSharedMemorySize, SM128);
    cudaFuncSetAttribute(mma_gemm<64, 3>,  cudaFuncAttributeMaxDynamicSharedMemorySize, SM64);

    const int nwblk  = (NN + 7) / 8;
    const int tnwblk = (TN + 7) / 8;
    const int teblk  = (TE + 255) / 256;
    const int tnblk  = (TN + 255) / 256;

    // ---------------- weight prep ----------------
    {
        WPArgs wa;
        wa.src[0] = W_ih; wa.n[0] = 12288; wa.base[0] = WIH;
        wa.src[1] = W_hh; wa.n[1] = 49152; wa.base[1] = WHH;
        wa.src[2] = cWq;  wa.n[2] = 32768; wa.base[2] = WQ;
        wa.src[3] = cWk;  wa.n[3] = 32768; wa.base[3] = WK;
        wa.src[4] = cWv;  wa.n[4] = 32768; wa.base[4] = WV;
        wa.src[5] = cWs;  wa.n[5] = 32768; wa.base[5] = WS;
        wprep_all<<<dim3((49152 + 255) / 256, 6), 256>>>(wa, wp);
    }

    // ---------------- GRU ----------------
    cudaMemsetAsync(phprev, 0, (size_t)NN * HID * sizeof(float));
    {
        PArgs pa;
        for (int p = 0; p < 3; p++) {
            pa.w[p] = wp + WIH + (size_t)p * 128 * 32;
            pa.lvl[p] = 12288;
            pa.bias[p] = b_ih + p * 128;
            pa.out[p] = pgi; pa.col[p] = p * 128; pa.ldc[p] = G3;
        }
        pa.w[3] = pa.w[2]; pa.lvl[3] = 12288; pa.bias[3] = pa.bias[2];
        pa.out[3] = pgi; pa.col[3] = 256; pa.ldc[3] = G3;
        mma_gemm<128, 2><<<(TN + 127) / 128, 256, SM128>>>(pa, x_seq, TN, 32, 3,
                                                           nullptr, nullptr, nullptr);
    }
    {
        PArgs pa;
        for (int p = 0; p < 3; p++) {
            pa.w[p] = wp + WHH + (size_t)p * 128 * 128;
            pa.lvl[p] = 49152;
            pa.bias[p] = b_hh + p * 128;
            pa.out[p] = pgh; pa.col[p] = p * 128; pa.ldc[p] = G3;
        }
        pa.w[3] = pa.w[2]; pa.lvl[3] = 49152; pa.bias[3] = pa.bias[2];
        pa.out[3] = pgh; pa.col[3] = 256; pa.ldc[3] = G3;
        for (int t = 0; t < T_STEPS; t++) {
            mma_gemm<64, 3><<<(NN + 63) / 64, 256, SM64>>>(
                pa, phprev, NN, 128, 3,
                pgi + (size_t)t * NN * G3, phprev, ph + (size_t)t * NN * HID);
        }
    }

    // ---------------- CSR build ----------------
    cudaMemsetAsync(pcnt, 0, TN * sizeof(int));
    csr_count<<<teblk, 256>>>(ei, pcnt);
    scan1<<<NBLK_SCAN, SCAN_B>>>(pcnt, pcur, pbsum);
    scan2<<<1, 256>>>(pbsum);
    scan3<<<tnblk, 256>>>(pcnt, pcur, pbsum, pstart, pcur);
    csr_scatter<<<teblk, 256>>>(ei, ea, pcur, pcsrc, pcea);

    // ---------------- GNN: 2 layers, batched over all T ----------------
    for (int l = 0; l < 2; l++) {
        const float* in  = (l == 0) ? ph : ptmp;
        float*       out = (l == 0) ? ptmp : ph;
        const float* We = cWe + (size_t)l * HID;
        size_t lo = (size_t)l * 16384;

        PArgs pa;
        pa.w[0] = wp + WQ + lo; pa.lvl[0] = 32768; pa.bias[0] = cbq + l * 128;
        pa.out[0] = pq;  pa.col[0] = 0; pa.ldc[0] = 128;
        pa.w[1] = wp + WK + lo; pa.lvl[1] = 32768; pa.bias[1] = cbk + l * 128;
        pa.out[1] = pk;  pa.col[1] = 0; pa.ldc[1] = 128;
        pa.w[2] = wp + WV + lo; pa.lvl[2] = 32768; pa.bias[2] = cbv + l * 128;
        pa.out[2] = pv;  pa.col[2] = 0; pa.ldc[2] = 128;
        pa.w[3] = wp + WS + lo; pa.lvl[3] = 32768; pa.bias[3] = cbs + l * 128;
        pa.out[3] = out; pa.col[3] = 0; pa.ldc[3] = 128;
        mma_gemm<128, 2><<<(TN + 127) / 128, 256, SM128>>>(pa, in, TN, 128, 4,
                                                           nullptr, nullptr, nullptr);

        conv_edge<<<tnwblk, 256>>>(pq, pk, pv, We, pstart, pcnt, pcsrc, pcea, out);
    }

    // ---------------- temporal attention + top-3 + output conv ----------------
    attn_outproj<<<nwblk, 256>>>(ph, aW, ab, oWq, obq, oWk, obk, oWv, obv,
                                 oWs, obs, pqs, pks, pvs, outp);
    oc_edge<<<nwblk, 256>>>(pqs, pks, pvs, oWe, pstart, pcnt, pcsrc, pcea, outp);
}